// round 8
// baseline (speedup 1.0000x reference)
#include <cuda_runtime.h>
#include <cuda_bf16.h>
#include <cstdint>

// Problem constants
constexpr int N_TOK = 3072;
constexpr int D     = 1280;
constexpr int H     = 16;
constexpr int HK    = 80;     // head dim
constexpr int WPR   = HK / 2; // packed bf16 words per row (40)
constexpr int NSEG  = 8;
constexpr float SCALE = 0.111803398874989485f; // 80^-0.5

// ---------------- scratch ----------------
__device__ uint32_t g_hid_tf[N_TOK * D];        // tf32 of hidden, k-interleaved
__device__ uint32_t g_qkvw_tf[D * 3 * D];       // tf32 of qkv_w (plain)
__device__ uint32_t g_projw_tf[D * D];          // tf32 of proj_w (plain)
__device__ float    g_qkv[N_TOK * 3 * D];       // [N][3][H][K] fp32
__device__ uint32_t g_qhib[H * N_TOK * WPR];    // bf16x2 hi of SCALE*rope(q)
__device__ uint32_t g_qlob[H * N_TOK * WPR];
__device__ uint32_t g_khib[H * N_TOK * WPR];
__device__ uint32_t g_klob[H * N_TOK * WPR];
__device__ uint32_t g_vtf[H * N_TOK * HK];      // tf32 v
__device__ uint32_t g_attn_tf[N_TOK * D];       // tf32 attn out, k-interleaved

// ---------------- helpers ----------------
__device__ __forceinline__ uint32_t f2tf32(float x) {
    uint32_t r;
    asm("cvt.rna.tf32.f32 %0, %1;" : "=r"(r) : "f"(x));
    return r;
}
__device__ __forceinline__ void mma_tf32(float c[4], const uint32_t a[4], const uint32_t b[2]) {
    asm volatile(
        "mma.sync.aligned.m16n8k8.row.col.f32.tf32.tf32.f32 "
        "{%0,%1,%2,%3}, {%4,%5,%6,%7}, {%8,%9}, {%0,%1,%2,%3};"
        : "+f"(c[0]), "+f"(c[1]), "+f"(c[2]), "+f"(c[3])
        : "r"(a[0]), "r"(a[1]), "r"(a[2]), "r"(a[3]), "r"(b[0]), "r"(b[1]));
}
__device__ __forceinline__ void mma_bf16(float c[4], const uint32_t a[4], const uint32_t b[2]) {
    asm volatile(
        "mma.sync.aligned.m16n8k16.row.col.f32.bf16.bf16.f32 "
        "{%0,%1,%2,%3}, {%4,%5,%6,%7}, {%8,%9}, {%0,%1,%2,%3};"
        : "+f"(c[0]), "+f"(c[1]), "+f"(c[2]), "+f"(c[3])
        : "r"(a[0]), "r"(a[1]), "r"(a[2]), "r"(a[3]), "r"(b[0]), "r"(b[1]));
}
__device__ __forceinline__ uint32_t bf16bits(float x) {
    const __nv_bfloat16 b = __float2bfloat16(x);
    return (uint32_t)*reinterpret_cast<const uint16_t*>(&b);
}
__device__ __forceinline__ float bf16val(uint32_t bits) {
    const uint16_t u = (uint16_t)bits;
    return __bfloat162float(*reinterpret_cast<const __nv_bfloat16*>(&u));
}
__device__ __forceinline__ uint32_t smem_addr(const void* p) {
    return (uint32_t)__cvta_generic_to_shared(p);
}
#define CP_ASYNC16(dst, src) \
    asm volatile("cp.async.cg.shared.global [%0], [%1], 16;" :: "r"(dst), "l"(src))
#define CP_COMMIT() asm volatile("cp.async.commit_group;")
#define CP_WAIT1()  asm volatile("cp.async.wait_group 1;")

// ---------------- converts ----------------
// plain f32 -> tf32 (weights)
__global__ void __launch_bounds__(256) f32_to_tf32_kernel(
    const float* __restrict__ s, uint32_t* __restrict__ d, int n4)
{
    const int i = blockIdx.x * blockDim.x + threadIdx.x;
    if (i >= n4) return;
    const float4 x = reinterpret_cast<const float4*>(s)[i];
    uint4 y;
    y.x = f2tf32(x.x); y.y = f2tf32(x.y); y.z = f2tf32(x.z); y.w = f2tf32(x.w);
    reinterpret_cast<uint4*>(d)[i] = y;
}

// f32 -> tf32 with k-interleave within groups of 8: out = [l0,l4,l1,l5,l2,l6,l3,l7]
__global__ void __launch_bounds__(256) f32_to_tf32_perm_kernel(
    const float* __restrict__ s, uint32_t* __restrict__ d, int n8)
{
    const int i = blockIdx.x * blockDim.x + threadIdx.x;
    if (i >= n8) return;
    const float4 x0 = reinterpret_cast<const float4*>(s)[2 * i];
    const float4 x1 = reinterpret_cast<const float4*>(s)[2 * i + 1];
    uint4 y0, y1;
    y0.x = f2tf32(x0.x); y0.y = f2tf32(x1.x); y0.z = f2tf32(x0.y); y0.w = f2tf32(x1.y);
    y1.x = f2tf32(x0.z); y1.y = f2tf32(x1.z); y1.z = f2tf32(x0.w); y1.w = f2tf32(x1.w);
    reinterpret_cast<uint4*>(d)[2 * i]     = y0;
    reinterpret_cast<uint4*>(d)[2 * i + 1] = y1;
}

// ---------------- tf32 GEMM, cp.async 3-stage, v2 A-fragment loads ----------------
// A is k-interleaved (pairs (k, k+4) adjacent). ASTR=40: v2 loads conflict-free.
constexpr int ASTR = 40;
constexpr int BSTR = 136;
constexpr int A_WORDS = 128 * ASTR;          // 5120
constexpr int B_WORDS = 32 * BSTR;           // 4352
constexpr int STAGE_WORDS = A_WORDS + B_WORDS;
constexpr int GEMM_SMEM = 3 * STAGE_WORDS * 4;   // 113,664 B

template<int NN, int KD>
__global__ void __launch_bounds__(256) tgemm_tf32_kernel(
    const uint32_t* __restrict__ A, const uint32_t* __restrict__ B,
    const float* __restrict__ bias, float* __restrict__ C)
{
    extern __shared__ uint32_t smem[];

    const int tid  = threadIdx.x;
    const int lane = tid & 31;
    const int w    = tid >> 5;
    const int g    = lane >> 2;
    const int qd   = lane & 3;
    const int wm   = w >> 2;
    const int wn   = w & 3;
    const int bm   = blockIdx.y * 128;
    const int bn   = blockIdx.x * 128;

    const int ar = tid >> 1;
    const int ah = (tid & 1) * 16;
    const int br = tid >> 3;
    const int bc = tid & 7;

    auto issue = [&](int kt) {
        const int k0 = kt * 32;
        uint32_t* as = smem + (kt % 3) * STAGE_WORDS;
        uint32_t* bs = as + A_WORDS;
        #pragma unroll
        for (int i = 0; i < 4; i++) {
            const uint32_t dst = smem_addr(&as[ar * ASTR + ah + i * 4]);
            CP_ASYNC16(dst, &A[(size_t)(bm + ar) * KD + k0 + ah + i * 4]);
        }
        #pragma unroll
        for (int i = 0; i < 4; i++) {
            const int col = (bc + 8 * i) * 4;
            const uint32_t dst = smem_addr(&bs[br * BSTR + col]);
            CP_ASYNC16(dst, &B[(size_t)(k0 + br) * NN + bn + col]);
        }
        CP_COMMIT();
    };

    float acc[4][4][4] = {};

    issue(0);
    issue(1);

    constexpr int KT = KD / 32;
    for (int kt = 0; kt < KT; kt++) {
        CP_WAIT1();
        __syncthreads();
        if (kt + 2 < KT) issue(kt + 2);

        const uint32_t* as = smem + (kt % 3) * STAGE_WORDS;
        const uint32_t* bs = as + A_WORDS;

        #pragma unroll
        for (int kk = 0; kk < 32; kk += 8) {
            uint32_t af[4][4], bf[4][2];
            #pragma unroll
            for (int mi = 0; mi < 4; mi++) {
                const int r0 = (wm * 64 + mi * 16 + g) * ASTR;
                const uint2 pa = *reinterpret_cast<const uint2*>(&as[r0 + kk + 2 * qd]);
                const uint2 pb = *reinterpret_cast<const uint2*>(&as[r0 + 8 * ASTR + kk + 2 * qd]);
                af[mi][0] = pa.x; af[mi][2] = pa.y;
                af[mi][1] = pb.x; af[mi][3] = pb.y;
            }
            #pragma unroll
            for (int ni = 0; ni < 4; ni++) {
                const int c0 = wn * 32 + ni * 8 + g;
                bf[ni][0] = bs[(kk + qd) * BSTR + c0];
                bf[ni][1] = bs[(kk + 4 + qd) * BSTR + c0];
            }
            #pragma unroll
            for (int mi = 0; mi < 4; mi++)
                #pragma unroll
                for (int ni = 0; ni < 4; ni++)
                    mma_tf32(acc[mi][ni], af[mi], bf[ni]);
        }
        // NOTE: no end-of-loop barrier — next iteration's CP_WAIT1+__syncthreads
        // orders all reads of stage kt%3 before issue(kt+3) overwrites it.
    }

    #pragma unroll
    for (int mi = 0; mi < 4; mi++) {
        const int row = bm + wm * 64 + mi * 16 + g;
        #pragma unroll
        for (int ni = 0; ni < 4; ni++) {
            const int col = bn + wn * 32 + ni * 8 + 2 * qd;
            const float2 bb = *reinterpret_cast<const float2*>(&bias[col]);
            float2 o0, o1;
            o0.x = acc[mi][ni][0] + bb.x; o0.y = acc[mi][ni][1] + bb.y;
            o1.x = acc[mi][ni][2] + bb.x; o1.y = acc[mi][ni][3] + bb.y;
            *reinterpret_cast<float2*>(&C[(size_t)row * NN + col]) = o0;
            *reinterpret_cast<float2*>(&C[(size_t)(row + 8) * NN + col]) = o1;
        }
    }
}

// ---------------- RoPE + split + bf16 hi/lo (q/k) + tf32 (v) ----------------
__global__ void __launch_bounds__(256) rope_split_kernel(
    const float* __restrict__ qkv, const float* __restrict__ cosNK,
    const float* __restrict__ sinNK,
    uint32_t* __restrict__ qhib, uint32_t* __restrict__ qlob,
    uint32_t* __restrict__ khib, uint32_t* __restrict__ klob,
    uint32_t* __restrict__ vtf)
{
    const int idx = blockIdx.x * blockDim.x + threadIdx.x;
    if (idx >= N_TOK * H * WPR) return;
    const int wd = idx % WPR;
    const int h  = (idx / WPR) % H;
    const int n  = idx / (WPR * H);

    const float* base = qkv + (size_t)n * 3 * H * HK;

    float qr[2], kr[2], vv[2];
    #pragma unroll
    for (int e = 0; e < 2; e++) {
        const int kk = 2 * wd + e;
        const float c = cosNK[n * HK + kk];
        const float s = sinNK[n * HK + kk];
        const int off  = h * HK + kk;
        const int krot = (kk < HK / 2) ? kk + HK / 2 : kk - HK / 2;
        const float sg = (kk < HK / 2) ? -1.f : 1.f;
        const int offr = h * HK + krot;
        const float qv  = base[off];
        const float kv  = base[H * HK + off];
        vv[e]           = base[2 * H * HK + off];
        const float qvr = base[offr];
        const float kvr = base[H * HK + offr];
        qr[e] = (qv * c + sg * qvr * s) * SCALE;
        kr[e] = kv * c + sg * kvr * s;
    }

    uint32_t qh[2], ql[2], kh[2], kl[2];
    #pragma unroll
    for (int e = 0; e < 2; e++) {
        qh[e] = bf16bits(qr[e]);
        ql[e] = bf16bits(qr[e] - bf16val(qh[e]));
        kh[e] = bf16bits(kr[e]);
        kl[e] = bf16bits(kr[e] - bf16val(kh[e]));
    }

    const size_t ow = (size_t)h * N_TOK * WPR + (size_t)n * WPR + wd;
    qhib[ow] = (qh[1] << 16) | qh[0];
    qlob[ow] = (ql[1] << 16) | ql[0];
    khib[ow] = (kh[1] << 16) | kh[0];
    klob[ow] = (kl[1] << 16) | kl[0];

    const size_t ov = (size_t)h * N_TOK * HK + (size_t)n * HK + 2 * wd;
    vtf[ov]     = f2tf32(vv[0]);
    vtf[ov + 1] = f2tf32(vv[1]);
}

// ---------------- mma flash attention: bf16 hi/lo QK, tf32 PV ----------------
constexpr int QTQ  = 64;
constexpr int KTK  = 32;
constexpr int QSTR = 44;
constexpr int VSTR = 88;
constexpr int PST  = 36;

constexpr int ATT_SMEM_WORDS =
    2 * QTQ * QSTR + 2 * KTK * QSTR + KTK * VSTR + 4 * 16 * PST + 2 * QTQ + 2;

__global__ void __launch_bounds__(128, 4) attn_mma_kernel(
    const uint32_t* __restrict__ gqhi, const uint32_t* __restrict__ gqlo,
    const uint32_t* __restrict__ gkhi, const uint32_t* __restrict__ gklo,
    const uint32_t* __restrict__ gvtf, const int* __restrict__ cu,
    uint32_t* __restrict__ attn_tf)
{
    extern __shared__ uint32_t sm[];
    uint32_t* qhiS = sm;
    uint32_t* qloS = qhiS + QTQ * QSTR;
    uint32_t* khiS = qloS + QTQ * QSTR;
    uint32_t* kloS = khiS + KTK * QSTR;
    uint32_t* vS   = kloS + KTK * QSTR;
    uint32_t* pS   = vS + KTK * VSTR;
    int*      rs   = (int*)(pS + 4 * 16 * PST);
    int*      re   = rs + QTQ;
    int*      blk  = re + QTQ;

    const int h    = blockIdx.y;
    const int q0   = blockIdx.x * QTQ;
    const int tid  = threadIdx.x;
    const int w    = tid >> 5;
    const int lane = tid & 31;
    const int g    = lane >> 2;
    const int qd   = lane & 3;

    if (tid < QTQ) {
        const int n = q0 + tid;
        int lo = 0, hi = N_TOK;
        #pragma unroll
        for (int sgi = 0; sgi < NSEG; sgi++) {
            const int a = cu[sgi], b = cu[sgi + 1];
            if (n >= a && n < b) { lo = a; hi = b; }
        }
        rs[tid] = lo; re[tid] = hi;
    }
    __syncthreads();
    if (tid == 0) {
        int lo = rs[0], hi = re[0];
        #pragma unroll
        for (int r = 1; r < QTQ; r++) { lo = min(lo, rs[r]); hi = max(hi, re[r]); }
        blk[0] = lo; blk[1] = hi;
    }

    int wlo = N_TOK, whi = 0;
    #pragma unroll
    for (int r = 0; r < 16; r++) {
        wlo = min(wlo, rs[w * 16 + r]);
        whi = max(whi, re[w * 16 + r]);
    }

    const size_t hb40 = (size_t)h * N_TOK * WPR;
    const size_t hb80 = (size_t)h * N_TOK * HK;
    for (int i = tid; i < QTQ * (WPR / 4); i += 128) {
        const int r  = i / (WPR / 4);
        const int c4 = (i % (WPR / 4)) * 4;
        const size_t go = hb40 + (size_t)(q0 + r) * WPR + c4;
        *reinterpret_cast<uint4*>(&qhiS[r * QSTR + c4]) = *reinterpret_cast<const uint4*>(&gqhi[go]);
        *reinterpret_cast<uint4*>(&qloS[r * QSTR + c4]) = *reinterpret_cast<const uint4*>(&gqlo[go]);
    }
    __syncthreads();

    const int rowA = w * 16 + g, rowB = rowA + 8;
    const int rsA = rs[rowA], reA = re[rowA];
    const int rsB = rs[rowB], reB = re[rowB];
    const int lo = blk[0], hi = blk[1];

    float miA = -1e30f, liA = 0.f, miB = -1e30f, liB = 0.f;
    float acc[10][4] = {};
    uint32_t* pw = pS + w * (16 * PST);

    for (int kc = lo; kc < hi; kc += KTK) {
        __syncthreads();
        for (int i = tid; i < KTK * (WPR / 4); i += 128) {
            const int r  = i / (WPR / 4);
            const int c4 = (i % (WPR / 4)) * 4;
            const int m  = kc + r;
            uint4 kh4 = {0, 0, 0, 0}, kl4 = {0, 0, 0, 0};
            if (m < hi) {
                const size_t go = hb40 + (size_t)m * WPR + c4;
                kh4 = *reinterpret_cast<const uint4*>(&gkhi[go]);
                kl4 = *reinterpret_cast<const uint4*>(&gklo[go]);
            }
            *reinterpret_cast<uint4*>(&khiS[r * QSTR + c4]) = kh4;
            *reinterpret_cast<uint4*>(&kloS[r * QSTR + c4]) = kl4;
        }
        for (int i = tid; i < KTK * (HK / 4); i += 128) {
            const int r  = i / (HK / 4);
            const int c4 = (i % (HK / 4)) * 4;
            const int m  = kc + r;
            uint4 vv4 = {0, 0, 0, 0};
            if (m < hi) {
                const size_t go = hb80 + (size_t)m * HK + c4;
                vv4 = *reinterpret_cast<const uint4*>(&gvtf[go]);
            }
            *reinterpret_cast<uint4*>(&vS[r * VSTR + c4]) = vv4;
        }
        __syncthreads();

        if (kc + KTK <= wlo || kc >= whi) continue;

        float s[4][4] = {};
        #pragma unroll
        for (int sl = 0; sl < 5; sl++) {
            const int base = sl * 8;
            uint32_t ah[4], al[4];
            const int rA = rowA * QSTR + base, rB = rowB * QSTR + base;
            ah[0] = qhiS[rA + qd];     ah[1] = qhiS[rB + qd];
            ah[2] = qhiS[rA + 4 + qd]; ah[3] = qhiS[rB + 4 + qd];
            al[0] = qloS[rA + qd];     al[1] = qloS[rB + qd];
            al[2] = qloS[rA + 4 + qd]; al[3] = qloS[rB + 4 + qd];
            #pragma unroll
            for (int nt = 0; nt < 4; nt++) {
                const int kr = (nt * 8 + g) * QSTR + base;
                uint32_t bh[2], bl[2];
                bh[0] = khiS[kr + qd]; bh[1] = khiS[kr + 4 + qd];
                bl[0] = kloS[kr + qd]; bl[1] = kloS[kr + 4 + qd];
                mma_bf16(s[nt], ah, bh);
                mma_bf16(s[nt], ah, bl);
                mma_bf16(s[nt], al, bh);
            }
        }

        float mxA = -1e30f, mxB = -1e30f;
        #pragma unroll
        for (int nt = 0; nt < 4; nt++) {
            const int c0 = kc + nt * 8 + 2 * qd;
            const int c1 = c0 + 1;
            mxA = fmaxf(mxA, fmaxf((c0 >= rsA && c0 < reA) ? s[nt][0] : -1e30f,
                                   (c1 >= rsA && c1 < reA) ? s[nt][1] : -1e30f));
            mxB = fmaxf(mxB, fmaxf((c0 >= rsB && c0 < reB) ? s[nt][2] : -1e30f,
                                   (c1 >= rsB && c1 < reB) ? s[nt][3] : -1e30f));
        }
        #pragma unroll
        for (int off = 1; off <= 2; off <<= 1) {
            mxA = fmaxf(mxA, __shfl_xor_sync(0xffffffffu, mxA, off));
            mxB = fmaxf(mxB, __shfl_xor_sync(0xffffffffu, mxB, off));
        }
        const float nmA = fmaxf(miA, mxA), nmB = fmaxf(miB, mxB);
        const float crA = __expf(miA - nmA), crB = __expf(miB - nmB);
        float sumA = 0.f, sumB = 0.f;
        #pragma unroll
        for (int nt = 0; nt < 4; nt++) {
            const int c0 = kc + nt * 8 + 2 * qd;
            const int c1 = c0 + 1;
            s[nt][0] = (c0 >= rsA && c0 < reA) ? __expf(s[nt][0] - nmA) : 0.f;
            s[nt][1] = (c1 >= rsA && c1 < reA) ? __expf(s[nt][1] - nmA) : 0.f;
            s[nt][2] = (c0 >= rsB && c0 < reB) ? __expf(s[nt][2] - nmB) : 0.f;
            s[nt][3] = (c1 >= rsB && c1 < reB) ? __expf(s[nt][3] - nmB) : 0.f;
            sumA += s[nt][0] + s[nt][1];
            sumB += s[nt][2] + s[nt][3];
        }
        #pragma unroll
        for (int off = 1; off <= 2; off <<= 1) {
            sumA += __shfl_xor_sync(0xffffffffu, sumA, off);
            sumB += __shfl_xor_sync(0xffffffffu, sumB, off);
        }
        liA = liA * crA + sumA; miA = nmA;
        liB = liB * crB + sumB; miB = nmB;

        #pragma unroll
        for (int nt = 0; nt < 10; nt++) {
            acc[nt][0] *= crA; acc[nt][1] *= crA;
            acc[nt][2] *= crB; acc[nt][3] *= crB;
        }

        #pragma unroll
        for (int nt = 0; nt < 4; nt++) {
            const int cb = nt * 8 + 2 * qd;
            uint2 pa, pb;
            pa.x = f2tf32(s[nt][0]); pa.y = f2tf32(s[nt][1]);
            pb.x = f2tf32(s[nt][2]); pb.y = f2tf32(s[nt][3]);
            *reinterpret_cast<uint2*>(&pw[g * PST + cb])       = pa;
            *reinterpret_cast<uint2*>(&pw[(g + 8) * PST + cb]) = pb;
        }
        __syncwarp();

        #pragma unroll
        for (int k8 = 0; k8 < KTK; k8 += 8) {
            uint32_t a[4];
            a[0] = pw[g * PST + k8 + qd];
            a[1] = pw[(g + 8) * PST + k8 + qd];
            a[2] = pw[g * PST + k8 + 4 + qd];
            a[3] = pw[(g + 8) * PST + k8 + 4 + qd];
            #pragma unroll
            for (int nt = 0; nt < 10; nt++) {
                uint32_t b[2];
                b[0] = vS[(k8 + qd) * VSTR + nt * 8 + g];
                b[1] = vS[(k8 + 4 + qd) * VSTR + nt * 8 + g];
                mma_tf32(acc[nt], a, b);
            }
        }
        __syncwarp();
    }

    // epilogue: normalize; write tf32 with k-interleave pos(j)=((j&3)<<1)|(j>>2)
    const float invA = 1.f / liA, invB = 1.f / liB;
    const int j0 = 2 * qd, j1 = 2 * qd + 1;
    const int p0 = ((j0 & 3) << 1) | (j0 >> 2);
    const int p1 = ((j1 & 3) << 1) | (j1 >> 2);
    uint32_t* dA = attn_tf + (size_t)(q0 + rowA) * D + h * HK;
    uint32_t* dB = attn_tf + (size_t)(q0 + rowB) * D + h * HK;
    #pragma unroll
    for (int nt = 0; nt < 10; nt++) {
        const int base = nt * 8;
        dA[base + p0] = f2tf32(acc[nt][0] * invA);
        dA[base + p1] = f2tf32(acc[nt][1] * invA);
        dB[base + p0] = f2tf32(acc[nt][2] * invB);
        dB[base + p1] = f2tf32(acc[nt][3] * invB);
    }
}

// ---------------- launch ----------------
extern "C" void kernel_launch(void* const* d_in, const int* in_sizes, int n_in,
                              void* d_out, int out_size)
{
    const float* hidden = (const float*)d_in[0];
    const int*   cu     = (const int*)  d_in[1];
    const float* cosNK  = (const float*)d_in[2];
    const float* sinNK  = (const float*)d_in[3];
    const float* qkv_w  = (const float*)d_in[4];
    const float* qkv_b  = (const float*)d_in[5];
    const float* proj_w = (const float*)d_in[6];
    const float* proj_b = (const float*)d_in[7];
    float* out = (float*)d_out;

    float *qkv;
    uint32_t *hidtf, *qkvwtf, *projwtf, *qhib, *qlob, *khib, *klob, *vtf, *attntf;
    cudaGetSymbolAddress((void**)&hidtf,  g_hid_tf);
    cudaGetSymbolAddress((void**)&qkvwtf, g_qkvw_tf);
    cudaGetSymbolAddress((void**)&projwtf,g_projw_tf);
    cudaGetSymbolAddress((void**)&qkv,    g_qkv);
    cudaGetSymbolAddress((void**)&qhib,   g_qhib);
    cudaGetSymbolAddress((void**)&qlob,   g_qlob);
    cudaGetSymbolAddress((void**)&khib,   g_khib);
    cudaGetSymbolAddress((void**)&klob,   g_klob);
    cudaGetSymbolAddress((void**)&vtf,    g_vtf);
    cudaGetSymbolAddress((void**)&attntf, g_attn_tf);

    const size_t attn_smem = ATT_SMEM_WORDS * sizeof(uint32_t);
    static bool attr_done = false;
    if (!attr_done) {
        cudaFuncSetAttribute(tgemm_tf32_kernel<3 * D, D>,
                             cudaFuncAttributeMaxDynamicSharedMemorySize, GEMM_SMEM);
        cudaFuncSetAttribute(tgemm_tf32_kernel<D, D>,
                             cudaFuncAttributeMaxDynamicSharedMemorySize, GEMM_SMEM);
        cudaFuncSetAttribute(attn_mma_kernel,
                             cudaFuncAttributeMaxDynamicSharedMemorySize, (int)attn_smem);
        attr_done = true;
    }

    // 0) converts: hidden k-interleaved; weights plain
    f32_to_tf32_perm_kernel<<<(N_TOK * D / 8 + 255) / 256, 256>>>(hidden, hidtf, N_TOK * D / 8);
    f32_to_tf32_kernel<<<(D * 3 * D / 4 + 255) / 256, 256>>>(qkv_w, qkvwtf, D * 3 * D / 4);
    f32_to_tf32_kernel<<<(D * D / 4 + 255) / 256, 256>>>(proj_w, projwtf, D * D / 4);

    // 1) QKV GEMM + bias
    tgemm_tf32_kernel<3 * D, D><<<dim3((3 * D) / 128, N_TOK / 128), 256, GEMM_SMEM>>>(
        hidtf, qkvwtf, qkv_b, qkv);

    // 2) RoPE + split + bf16 hi/lo + tf32 v
    rope_split_kernel<<<(N_TOK * H * WPR + 255) / 256, 256>>>(
        qkv, cosNK, sinNK, qhib, qlob, khib, klob, vtf);

    // 3) mma flash attention -> tf32 (k-interleaved) output
    attn_mma_kernel<<<dim3(N_TOK / QTQ, H), 128, attn_smem>>>(
        qhib, qlob, khib, klob, vtf, cu, attntf);

    // 4) projection GEMM + bias -> d_out
    tgemm_tf32_kernel<D, D><<<dim3(D / 128, N_TOK / 128), 256, GEMM_SMEM>>>(
        attntf, projwtf, proj_b, out);
}

// round 9
// speedup vs baseline: 1.1766x; 1.1766x over previous
#include <cuda_runtime.h>
#include <cuda_bf16.h>
#include <cstdint>

// Problem constants
constexpr int N_TOK = 3072;
constexpr int D     = 1280;
constexpr int H     = 16;
constexpr int HK    = 80;     // head dim
constexpr int WPR   = HK / 2; // packed bf16 words per row (40)
constexpr int NSEG  = 8;
constexpr float SCALE = 0.111803398874989485f; // 80^-0.5

// ---------------- scratch ----------------
__device__ uint32_t g_hid_tf[N_TOK * D];        // tf32 of hidden
__device__ uint32_t g_qkvw_tf[D * 3 * D];       // tf32 of qkv_w
__device__ uint32_t g_projw_tf[D * D];          // tf32 of proj_w
__device__ float    g_qkv[N_TOK * 3 * D];       // [N][3][H][K] fp32
__device__ uint32_t g_qhib[H * N_TOK * WPR];    // bf16x2 hi of SCALE*rope(q)
__device__ uint32_t g_qlob[H * N_TOK * WPR];
__device__ uint32_t g_khib[H * N_TOK * WPR];
__device__ uint32_t g_klob[H * N_TOK * WPR];
__device__ uint32_t g_vtf[H * N_TOK * HK];      // tf32 v
__device__ uint32_t g_attn_tf[N_TOK * D];       // tf32 attn out [N][H*K]

// ---------------- helpers ----------------
__device__ __forceinline__ uint32_t f2tf32(float x) {
    uint32_t r;
    asm("cvt.rna.tf32.f32 %0, %1;" : "=r"(r) : "f"(x));
    return r;
}
__device__ __forceinline__ void mma_tf32(float c[4], const uint32_t a[4], const uint32_t b[2]) {
    asm volatile(
        "mma.sync.aligned.m16n8k8.row.col.f32.tf32.tf32.f32 "
        "{%0,%1,%2,%3}, {%4,%5,%6,%7}, {%8,%9}, {%0,%1,%2,%3};"
        : "+f"(c[0]), "+f"(c[1]), "+f"(c[2]), "+f"(c[3])
        : "r"(a[0]), "r"(a[1]), "r"(a[2]), "r"(a[3]), "r"(b[0]), "r"(b[1]));
}
__device__ __forceinline__ void mma_bf16(float c[4], const uint32_t a[4], const uint32_t b[2]) {
    asm volatile(
        "mma.sync.aligned.m16n8k16.row.col.f32.bf16.bf16.f32 "
        "{%0,%1,%2,%3}, {%4,%5,%6,%7}, {%8,%9}, {%0,%1,%2,%3};"
        : "+f"(c[0]), "+f"(c[1]), "+f"(c[2]), "+f"(c[3])
        : "r"(a[0]), "r"(a[1]), "r"(a[2]), "r"(a[3]), "r"(b[0]), "r"(b[1]));
}
__device__ __forceinline__ uint32_t bf16bits(float x) {
    const __nv_bfloat16 b = __float2bfloat16(x);
    return (uint32_t)*reinterpret_cast<const uint16_t*>(&b);
}
__device__ __forceinline__ float bf16val(uint32_t bits) {
    const uint16_t u = (uint16_t)bits;
    return __bfloat162float(*reinterpret_cast<const __nv_bfloat16*>(&u));
}
__device__ __forceinline__ uint32_t smem_addr(const void* p) {
    return (uint32_t)__cvta_generic_to_shared(p);
}
#define CP_ASYNC16(dst, src) \
    asm volatile("cp.async.cg.shared.global [%0], [%1], 16;" :: "r"(dst), "l"(src))
#define CP_ASYNC16Z(dst, src, sz) \
    asm volatile("cp.async.cg.shared.global [%0], [%1], 16, %2;" :: "r"(dst), "l"(src), "r"(sz))
#define CP_COMMIT() asm volatile("cp.async.commit_group;")
#define CP_WAIT1()  asm volatile("cp.async.wait_group 1;")
#define CP_WAIT0()  asm volatile("cp.async.wait_group 0;")

// ---------------- f32 -> tf32 bulk convert ----------------
__global__ void __launch_bounds__(256) f32_to_tf32_kernel(
    const float* __restrict__ s, uint32_t* __restrict__ d, int n4)
{
    const int i = blockIdx.x * blockDim.x + threadIdx.x;
    if (i >= n4) return;
    const float4 x = reinterpret_cast<const float4*>(s)[i];
    uint4 y;
    y.x = f2tf32(x.x); y.y = f2tf32(x.y); y.z = f2tf32(x.z); y.w = f2tf32(x.w);
    reinterpret_cast<uint4*>(d)[i] = y;
}

// ---------------- tf32 GEMM, cp.async 3-stage (exact R6 version) ----------------
constexpr int ASTR = 36;
constexpr int BSTR = 136;
constexpr int A_WORDS = 128 * ASTR;
constexpr int B_WORDS = 32 * BSTR;
constexpr int STAGE_WORDS = A_WORDS + B_WORDS;
constexpr int GEMM_SMEM = 3 * STAGE_WORDS * 4;

template<int NN, int KD>
__global__ void __launch_bounds__(256) tgemm_tf32_kernel(
    const uint32_t* __restrict__ A, const uint32_t* __restrict__ B,
    const float* __restrict__ bias, float* __restrict__ C)
{
    extern __shared__ uint32_t smem[];

    const int tid  = threadIdx.x;
    const int lane = tid & 31;
    const int w    = tid >> 5;
    const int g    = lane >> 2;
    const int qd   = lane & 3;
    const int wm   = w >> 2;
    const int wn   = w & 3;
    const int bm   = blockIdx.y * 128;
    const int bn   = blockIdx.x * 128;

    const int ar = tid >> 1;
    const int ah = (tid & 1) * 16;
    const int br = tid >> 3;
    const int bc = tid & 7;

    auto issue = [&](int kt) {
        const int k0 = kt * 32;
        uint32_t* as = smem + (kt % 3) * STAGE_WORDS;
        uint32_t* bs = as + A_WORDS;
        #pragma unroll
        for (int i = 0; i < 4; i++) {
            const uint32_t dst = smem_addr(&as[ar * ASTR + ah + i * 4]);
            CP_ASYNC16(dst, &A[(size_t)(bm + ar) * KD + k0 + ah + i * 4]);
        }
        #pragma unroll
        for (int i = 0; i < 4; i++) {
            const int col = (bc + 8 * i) * 4;
            const uint32_t dst = smem_addr(&bs[br * BSTR + col]);
            CP_ASYNC16(dst, &B[(size_t)(k0 + br) * NN + bn + col]);
        }
        CP_COMMIT();
    };

    float acc[4][4][4] = {};

    issue(0);
    issue(1);

    constexpr int KT = KD / 32;
    for (int kt = 0; kt < KT; kt++) {
        CP_WAIT1();
        __syncthreads();
        if (kt + 2 < KT) issue(kt + 2);

        const uint32_t* as = smem + (kt % 3) * STAGE_WORDS;
        const uint32_t* bs = as + A_WORDS;

        #pragma unroll
        for (int kk = 0; kk < 32; kk += 8) {
            uint32_t af[4][4], bf[4][2];
            #pragma unroll
            for (int mi = 0; mi < 4; mi++) {
                const int r0 = (wm * 64 + mi * 16 + g) * ASTR;
                af[mi][0] = as[r0 + kk + qd];
                af[mi][1] = as[r0 + 8 * ASTR + kk + qd];
                af[mi][2] = as[r0 + kk + 4 + qd];
                af[mi][3] = as[r0 + 8 * ASTR + kk + 4 + qd];
            }
            #pragma unroll
            for (int ni = 0; ni < 4; ni++) {
                const int c0 = wn * 32 + ni * 8 + g;
                bf[ni][0] = bs[(kk + qd) * BSTR + c0];
                bf[ni][1] = bs[(kk + 4 + qd) * BSTR + c0];
            }
            #pragma unroll
            for (int mi = 0; mi < 4; mi++)
                #pragma unroll
                for (int ni = 0; ni < 4; ni++)
                    mma_tf32(acc[mi][ni], af[mi], bf[ni]);
        }
        __syncthreads();
    }

    #pragma unroll
    for (int mi = 0; mi < 4; mi++) {
        const int row = bm + wm * 64 + mi * 16 + g;
        #pragma unroll
        for (int ni = 0; ni < 4; ni++) {
            const int col = bn + wn * 32 + ni * 8 + 2 * qd;
            const float2 bb = *reinterpret_cast<const float2*>(&bias[col]);
            float2 o0, o1;
            o0.x = acc[mi][ni][0] + bb.x; o0.y = acc[mi][ni][1] + bb.y;
            o1.x = acc[mi][ni][2] + bb.x; o1.y = acc[mi][ni][3] + bb.y;
            *reinterpret_cast<float2*>(&C[(size_t)row * NN + col]) = o0;
            *reinterpret_cast<float2*>(&C[(size_t)(row + 8) * NN + col]) = o1;
        }
    }
}

// ---------------- RoPE + split + bf16 hi/lo (q/k) + tf32 (v) ----------------
__global__ void __launch_bounds__(256) rope_split_kernel(
    const float* __restrict__ qkv, const float* __restrict__ cosNK,
    const float* __restrict__ sinNK,
    uint32_t* __restrict__ qhib, uint32_t* __restrict__ qlob,
    uint32_t* __restrict__ khib, uint32_t* __restrict__ klob,
    uint32_t* __restrict__ vtf)
{
    const int idx = blockIdx.x * blockDim.x + threadIdx.x;
    if (idx >= N_TOK * H * WPR) return;
    const int wd = idx % WPR;
    const int h  = (idx / WPR) % H;
    const int n  = idx / (WPR * H);

    const float* base = qkv + (size_t)n * 3 * H * HK;

    float qr[2], kr[2], vv[2];
    #pragma unroll
    for (int e = 0; e < 2; e++) {
        const int kk = 2 * wd + e;
        const float c = cosNK[n * HK + kk];
        const float s = sinNK[n * HK + kk];
        const int off  = h * HK + kk;
        const int krot = (kk < HK / 2) ? kk + HK / 2 : kk - HK / 2;
        const float sg = (kk < HK / 2) ? -1.f : 1.f;
        const int offr = h * HK + krot;
        const float qv  = base[off];
        const float kv  = base[H * HK + off];
        vv[e]           = base[2 * H * HK + off];
        const float qvr = base[offr];
        const float kvr = base[H * HK + offr];
        qr[e] = (qv * c + sg * qvr * s) * SCALE;
        kr[e] = kv * c + sg * kvr * s;
    }

    uint32_t qh[2], ql[2], kh[2], kl[2];
    #pragma unroll
    for (int e = 0; e < 2; e++) {
        qh[e] = bf16bits(qr[e]);
        ql[e] = bf16bits(qr[e] - bf16val(qh[e]));
        kh[e] = bf16bits(kr[e]);
        kl[e] = bf16bits(kr[e] - bf16val(kh[e]));
    }

    const size_t ow = (size_t)h * N_TOK * WPR + (size_t)n * WPR + wd;
    qhib[ow] = (qh[1] << 16) | qh[0];
    qlob[ow] = (ql[1] << 16) | ql[0];
    khib[ow] = (kh[1] << 16) | kh[0];
    klob[ow] = (kl[1] << 16) | kl[0];

    const size_t ov = (size_t)h * N_TOK * HK + (size_t)n * HK + 2 * wd;
    vtf[ov]     = f2tf32(vv[0]);
    vtf[ov + 1] = f2tf32(vv[1]);
}

// ---------------- mma flash attention: Q in regs, cp.async double-buffered K/V ----------------
constexpr int QTQ  = 64;
constexpr int KTK  = 32;
constexpr int QSTR = 44;   // k smem stride (packed bf16x2 words)
constexpr int VSTR = 88;   // v smem stride
constexpr int PST  = 36;   // P stride

constexpr int ATT_SMEM_WORDS =
    2 * KTK * QSTR      // khi double-buffered   2816
    + 2 * KTK * QSTR    // klo                    2816
    + 2 * KTK * VSTR    // v                      5632
    + 4 * 16 * PST      // P                      2304
    + 2 * QTQ + 2;      // rs, re, blk

__global__ void __launch_bounds__(128, 3) attn_mma_kernel(
    const uint32_t* __restrict__ gqhi, const uint32_t* __restrict__ gqlo,
    const uint32_t* __restrict__ gkhi, const uint32_t* __restrict__ gklo,
    const uint32_t* __restrict__ gvtf, const int* __restrict__ cu,
    uint32_t* __restrict__ attn_tf)
{
    extern __shared__ uint32_t sm[];
    uint32_t* khiS = sm;                       // [2][KTK*QSTR]
    uint32_t* kloS = khiS + 2 * KTK * QSTR;
    uint32_t* vS   = kloS + 2 * KTK * QSTR;    // [2][KTK*VSTR]
    uint32_t* pS   = vS + 2 * KTK * VSTR;
    int*      rs   = (int*)(pS + 4 * 16 * PST);
    int*      re   = rs + QTQ;
    int*      blk  = re + QTQ;

    const int h    = blockIdx.y;
    const int q0   = blockIdx.x * QTQ;
    const int tid  = threadIdx.x;
    const int w    = tid >> 5;
    const int lane = tid & 31;
    const int g    = lane >> 2;
    const int qd   = lane & 3;

    if (tid < QTQ) {
        const int n = q0 + tid;
        int lo = 0, hi = N_TOK;
        #pragma unroll
        for (int sgi = 0; sgi < NSEG; sgi++) {
            const int a = cu[sgi], b = cu[sgi + 1];
            if (n >= a && n < b) { lo = a; hi = b; }
        }
        rs[tid] = lo; re[tid] = hi;
    }
    __syncthreads();
    if (tid == 0) {
        int lo = rs[0], hi = re[0];
        #pragma unroll
        for (int r = 1; r < QTQ; r++) { lo = min(lo, rs[r]); hi = max(hi, re[r]); }
        blk[0] = lo; blk[1] = hi;
    }

    // per-warp bounds + per-row bounds (rs/re valid after first barrier)
    int wlo = N_TOK, whi = 0;
    #pragma unroll
    for (int r = 0; r < 16; r++) {
        wlo = min(wlo, rs[w * 16 + r]);
        whi = max(whi, re[w * 16 + r]);
    }
    const int rowA = w * 16 + g, rowB = rowA + 8;
    const int rsA = rs[rowA], reA = re[rowA];
    const int rsB = rs[rowB], reB = re[rowB];

    // Q fragments -> registers (one-time global loads)
    const size_t hb40 = (size_t)h * N_TOK * WPR;
    const size_t hb80 = (size_t)h * N_TOK * HK;
    uint32_t qh[5][4], ql[5][4];
    #pragma unroll
    for (int sl = 0; sl < 5; sl++) {
        const size_t bA = hb40 + (size_t)(q0 + rowA) * WPR + sl * 8;
        const size_t bB = hb40 + (size_t)(q0 + rowB) * WPR + sl * 8;
        qh[sl][0] = gqhi[bA + qd];     qh[sl][1] = gqhi[bB + qd];
        qh[sl][2] = gqhi[bA + 4 + qd]; qh[sl][3] = gqhi[bB + 4 + qd];
        ql[sl][0] = gqlo[bA + qd];     ql[sl][1] = gqlo[bB + qd];
        ql[sl][2] = gqlo[bA + 4 + qd]; ql[sl][3] = gqlo[bB + 4 + qd];
    }
    __syncthreads();                 // blk visible
    const int lo = blk[0], hi = blk[1];

    auto stageKV = [&](int kc, int buf) {
        uint32_t* kh_ = khiS + buf * KTK * QSTR;
        uint32_t* kl_ = kloS + buf * KTK * QSTR;
        uint32_t* v_  = vS + buf * KTK * VSTR;
        for (int i = tid; i < KTK * 10; i += 128) {      // 10 uint4 per k-row
            const int r = i / 10, c = (i % 10) * 4;
            const int m = kc + r;
            const uint32_t sz = (m < hi) ? 16u : 0u;
            const size_t go = hb40 + (size_t)min(m, hi - 1) * WPR + c;
            CP_ASYNC16Z(smem_addr(&kh_[r * QSTR + c]), &gkhi[go], sz);
            CP_ASYNC16Z(smem_addr(&kl_[r * QSTR + c]), &gklo[go], sz);
        }
        for (int i = tid; i < KTK * 20; i += 128) {      // 20 uint4 per v-row
            const int r = i / 20, c = (i % 20) * 4;
            const int m = kc + r;
            const uint32_t sz = (m < hi) ? 16u : 0u;
            const size_t go = hb80 + (size_t)min(m, hi - 1) * HK + c;
            CP_ASYNC16Z(smem_addr(&v_[r * VSTR + c]), &gvtf[go], sz);
        }
        CP_COMMIT();
    };

    float miA = -1e30f, liA = 0.f, miB = -1e30f, liB = 0.f;
    float acc[10][4] = {};
    uint32_t* pw = pS + w * (16 * PST);

    const int T = (hi - lo + KTK - 1) / KTK;
    stageKV(lo, 0);

    for (int t = 0; t < T; t++) {
        const int kc  = lo + t * KTK;
        const int buf = t & 1;
        // next stage writes buf^1, last computed at t-1; trailing barrier orders it.
        if (t + 1 < T) { stageKV(kc + KTK, buf ^ 1); CP_WAIT1(); }
        else           { CP_WAIT0(); }
        __syncthreads();

        if (!(kc + KTK <= wlo || kc >= whi)) {
            const uint32_t* kh_ = khiS + buf * KTK * QSTR;
            const uint32_t* kl_ = kloS + buf * KTK * QSTR;
            const uint32_t* v_  = vS + buf * KTK * VSTR;

            // ---- S = Q K^T (3x bf16 hi/lo) ----
            float s[4][4] = {};
            #pragma unroll
            for (int sl = 0; sl < 5; sl++) {
                const int base = sl * 8;
                #pragma unroll
                for (int nt = 0; nt < 4; nt++) {
                    const int kr = (nt * 8 + g) * QSTR + base;
                    uint32_t bh[2], bl[2];
                    bh[0] = kh_[kr + qd]; bh[1] = kh_[kr + 4 + qd];
                    bl[0] = kl_[kr + qd]; bl[1] = kl_[kr + 4 + qd];
                    mma_bf16(s[nt], qh[sl], bh);
                    mma_bf16(s[nt], qh[sl], bl);
                    mma_bf16(s[nt], ql[sl], bh);
                }
            }

            // ---- register softmax ----
            float mxA = -1e30f, mxB = -1e30f;
            #pragma unroll
            for (int nt = 0; nt < 4; nt++) {
                const int c0 = kc + nt * 8 + 2 * qd;
                const int c1 = c0 + 1;
                mxA = fmaxf(mxA, fmaxf((c0 >= rsA && c0 < reA) ? s[nt][0] : -1e30f,
                                       (c1 >= rsA && c1 < reA) ? s[nt][1] : -1e30f));
                mxB = fmaxf(mxB, fmaxf((c0 >= rsB && c0 < reB) ? s[nt][2] : -1e30f,
                                       (c1 >= rsB && c1 < reB) ? s[nt][3] : -1e30f));
            }
            #pragma unroll
            for (int off = 1; off <= 2; off <<= 1) {
                mxA = fmaxf(mxA, __shfl_xor_sync(0xffffffffu, mxA, off));
                mxB = fmaxf(mxB, __shfl_xor_sync(0xffffffffu, mxB, off));
            }
            const float nmA = fmaxf(miA, mxA), nmB = fmaxf(miB, mxB);
            const float crA = __expf(miA - nmA), crB = __expf(miB - nmB);
            float sumA = 0.f, sumB = 0.f;
            #pragma unroll
            for (int nt = 0; nt < 4; nt++) {
                const int c0 = kc + nt * 8 + 2 * qd;
                const int c1 = c0 + 1;
                s[nt][0] = (c0 >= rsA && c0 < reA) ? __expf(s[nt][0] - nmA) : 0.f;
                s[nt][1] = (c1 >= rsA && c1 < reA) ? __expf(s[nt][1] - nmA) : 0.f;
                s[nt][2] = (c0 >= rsB && c0 < reB) ? __expf(s[nt][2] - nmB) : 0.f;
                s[nt][3] = (c1 >= rsB && c1 < reB) ? __expf(s[nt][3] - nmB) : 0.f;
                sumA += s[nt][0] + s[nt][1];
                sumB += s[nt][2] + s[nt][3];
            }
            #pragma unroll
            for (int off = 1; off <= 2; off <<= 1) {
                sumA += __shfl_xor_sync(0xffffffffu, sumA, off);
                sumB += __shfl_xor_sync(0xffffffffu, sumB, off);
            }
            liA = liA * crA + sumA; miA = nmA;
            liB = liB * crB + sumB; miB = nmB;

            #pragma unroll
            for (int nt = 0; nt < 10; nt++) {
                acc[nt][0] *= crA; acc[nt][1] *= crA;
                acc[nt][2] *= crB; acc[nt][3] *= crB;
            }

            // ---- P -> warp-private smem (tf32), then PV (tf32) ----
            #pragma unroll
            for (int nt = 0; nt < 4; nt++) {
                const int cb = nt * 8 + 2 * qd;
                uint2 pa, pb;
                pa.x = f2tf32(s[nt][0]); pa.y = f2tf32(s[nt][1]);
                pb.x = f2tf32(s[nt][2]); pb.y = f2tf32(s[nt][3]);
                *reinterpret_cast<uint2*>(&pw[g * PST + cb])       = pa;
                *reinterpret_cast<uint2*>(&pw[(g + 8) * PST + cb]) = pb;
            }
            __syncwarp();

            #pragma unroll
            for (int k8 = 0; k8 < KTK; k8 += 8) {
                uint32_t a[4];
                a[0] = pw[g * PST + k8 + qd];
                a[1] = pw[(g + 8) * PST + k8 + qd];
                a[2] = pw[g * PST + k8 + 4 + qd];
                a[3] = pw[(g + 8) * PST + k8 + 4 + qd];
                #pragma unroll
                for (int nt = 0; nt < 10; nt++) {
                    uint32_t b[2];
                    b[0] = v_[(k8 + qd) * VSTR + nt * 8 + g];
                    b[1] = v_[(k8 + 4 + qd) * VSTR + nt * 8 + g];
                    mma_tf32(acc[nt], a, b);
                }
            }
            __syncwarp();
        }
        __syncthreads();   // compute(t) done before stage at t+1 overwrites buf^1
    }

    // ---- epilogue: normalize, write tf32 [N][H*K] ----
    const float invA = 1.f / liA, invB = 1.f / liB;
    uint32_t* dA = attn_tf + (size_t)(q0 + rowA) * D + h * HK;
    uint32_t* dB = attn_tf + (size_t)(q0 + rowB) * D + h * HK;
    #pragma unroll
    for (int nt = 0; nt < 10; nt++) {
        const int col = nt * 8 + 2 * qd;
        dA[col]     = f2tf32(acc[nt][0] * invA);
        dA[col + 1] = f2tf32(acc[nt][1] * invA);
        dB[col]     = f2tf32(acc[nt][2] * invB);
        dB[col + 1] = f2tf32(acc[nt][3] * invB);
    }
}

// ---------------- launch ----------------
extern "C" void kernel_launch(void* const* d_in, const int* in_sizes, int n_in,
                              void* d_out, int out_size)
{
    const float* hidden = (const float*)d_in[0];
    const int*   cu     = (const int*)  d_in[1];
    const float* cosNK  = (const float*)d_in[2];
    const float* sinNK  = (const float*)d_in[3];
    const float* qkv_w  = (const float*)d_in[4];
    const float* qkv_b  = (const float*)d_in[5];
    const float* proj_w = (const float*)d_in[6];
    const float* proj_b = (const float*)d_in[7];
    float* out = (float*)d_out;

    float *qkv;
    uint32_t *hidtf, *qkvwtf, *projwtf, *qhib, *qlob, *khib, *klob, *vtf, *attntf;
    cudaGetSymbolAddress((void**)&hidtf,  g_hid_tf);
    cudaGetSymbolAddress((void**)&qkvwtf, g_qkvw_tf);
    cudaGetSymbolAddress((void**)&projwtf,g_projw_tf);
    cudaGetSymbolAddress((void**)&qkv,    g_qkv);
    cudaGetSymbolAddress((void**)&qhib,   g_qhib);
    cudaGetSymbolAddress((void**)&qlob,   g_qlob);
    cudaGetSymbolAddress((void**)&khib,   g_khib);
    cudaGetSymbolAddress((void**)&klob,   g_klob);
    cudaGetSymbolAddress((void**)&vtf,    g_vtf);
    cudaGetSymbolAddress((void**)&attntf, g_attn_tf);

    const size_t attn_smem = ATT_SMEM_WORDS * sizeof(uint32_t);
    static bool attr_done = false;
    if (!attr_done) {
        cudaFuncSetAttribute(tgemm_tf32_kernel<3 * D, D>,
                             cudaFuncAttributeMaxDynamicSharedMemorySize, GEMM_SMEM);
        cudaFuncSetAttribute(tgemm_tf32_kernel<D, D>,
                             cudaFuncAttributeMaxDynamicSharedMemorySize, GEMM_SMEM);
        cudaFuncSetAttribute(attn_mma_kernel,
                             cudaFuncAttributeMaxDynamicSharedMemorySize, (int)attn_smem);
        attr_done = true;
    }

    // 0) converts
    f32_to_tf32_kernel<<<(N_TOK * D / 4 + 255) / 256, 256>>>(hidden, hidtf, N_TOK * D / 4);
    f32_to_tf32_kernel<<<(D * 3 * D / 4 + 255) / 256, 256>>>(qkv_w, qkvwtf, D * 3 * D / 4);
    f32_to_tf32_kernel<<<(D * D / 4 + 255) / 256, 256>>>(proj_w, projwtf, D * D / 4);

    // 1) QKV GEMM + bias
    tgemm_tf32_kernel<3 * D, D><<<dim3((3 * D) / 128, N_TOK / 128), 256, GEMM_SMEM>>>(
        hidtf, qkvwtf, qkv_b, qkv);

    // 2) RoPE + split + bf16 hi/lo + tf32 v
    rope_split_kernel<<<(N_TOK * H * WPR + 255) / 256, 256>>>(
        qkv, cosNK, sinNK, qhib, qlob, khib, klob, vtf);

    // 3) mma flash attention (Q-in-regs, double-buffered K/V) -> tf32 output
    attn_mma_kernel<<<dim3(N_TOK / QTQ, H), 128, attn_smem>>>(
        qhib, qlob, khib, klob, vtf, cu, attntf);

    // 4) projection GEMM + bias -> d_out
    tgemm_tf32_kernel<D, D><<<dim3(D / 128, N_TOK / 128), 256, GEMM_SMEM>>>(
        attntf, projwtf, proj_b, out);
}

// round 10
// speedup vs baseline: 1.1854x; 1.0075x over previous
#include <cuda_runtime.h>
#include <cuda_bf16.h>
#include <cstdint>

// Problem constants
constexpr int N_TOK = 3072;
constexpr int D     = 1280;
constexpr int H     = 16;
constexpr int HK    = 80;     // head dim
constexpr int WPR   = HK / 2; // packed bf16 words per row (40)
constexpr int NSEG  = 8;
constexpr float SCALE = 0.111803398874989485f; // 80^-0.5

// ---------------- scratch ----------------
__device__ uint32_t g_hid_tf[N_TOK * D];        // tf32 of hidden
__device__ uint32_t g_qkvw_tf[D * 3 * D];       // tf32 of qkv_w
__device__ uint32_t g_projw_tf[D * D];          // tf32 of proj_w
__device__ float    g_qkv[N_TOK * 3 * D];       // [N][3][H][K] fp32
__device__ uint32_t g_qhib[H * N_TOK * WPR];    // bf16x2 hi of SCALE*rope(q)
__device__ uint32_t g_qlob[H * N_TOK * WPR];
__device__ uint32_t g_khib[H * N_TOK * WPR];
__device__ uint32_t g_klob[H * N_TOK * WPR];
__device__ uint32_t g_vtf[H * N_TOK * HK];      // tf32 v
__device__ uint32_t g_attn_tf[N_TOK * D];       // tf32 attn out [N][H*K]

// ---------------- helpers ----------------
__device__ __forceinline__ uint32_t f2tf32(float x) {
    uint32_t r;
    asm("cvt.rna.tf32.f32 %0, %1;" : "=r"(r) : "f"(x));
    return r;
}
__device__ __forceinline__ void mma_tf32(float c[4], const uint32_t a[4], const uint32_t b[2]) {
    asm volatile(
        "mma.sync.aligned.m16n8k8.row.col.f32.tf32.tf32.f32 "
        "{%0,%1,%2,%3}, {%4,%5,%6,%7}, {%8,%9}, {%0,%1,%2,%3};"
        : "+f"(c[0]), "+f"(c[1]), "+f"(c[2]), "+f"(c[3])
        : "r"(a[0]), "r"(a[1]), "r"(a[2]), "r"(a[3]), "r"(b[0]), "r"(b[1]));
}
__device__ __forceinline__ void mma_bf16(float c[4], const uint32_t a[4], const uint32_t b[2]) {
    asm volatile(
        "mma.sync.aligned.m16n8k16.row.col.f32.bf16.bf16.f32 "
        "{%0,%1,%2,%3}, {%4,%5,%6,%7}, {%8,%9}, {%0,%1,%2,%3};"
        : "+f"(c[0]), "+f"(c[1]), "+f"(c[2]), "+f"(c[3])
        : "r"(a[0]), "r"(a[1]), "r"(a[2]), "r"(a[3]), "r"(b[0]), "r"(b[1]));
}
__device__ __forceinline__ uint32_t bf16bits(float x) {
    const __nv_bfloat16 b = __float2bfloat16(x);
    return (uint32_t)*reinterpret_cast<const uint16_t*>(&b);
}
__device__ __forceinline__ float bf16val(uint32_t bits) {
    const uint16_t u = (uint16_t)bits;
    return __bfloat162float(*reinterpret_cast<const __nv_bfloat16*>(&u));
}
__device__ __forceinline__ uint32_t smem_addr(const void* p) {
    return (uint32_t)__cvta_generic_to_shared(p);
}
#define CP_ASYNC16(dst, src) \
    asm volatile("cp.async.cg.shared.global [%0], [%1], 16;" :: "r"(dst), "l"(src))
#define CP_ASYNC16Z(dst, src, sz) \
    asm volatile("cp.async.cg.shared.global [%0], [%1], 16, %2;" :: "r"(dst), "l"(src), "r"(sz))
#define CP_COMMIT() asm volatile("cp.async.commit_group;")
#define CP_WAIT1()  asm volatile("cp.async.wait_group 1;")
#define CP_WAIT0()  asm volatile("cp.async.wait_group 0;")

// ---------------- f32 -> tf32 bulk convert ----------------
__global__ void __launch_bounds__(256) f32_to_tf32_kernel(
    const float* __restrict__ s, uint32_t* __restrict__ d, int n4)
{
    const int i = blockIdx.x * blockDim.x + threadIdx.x;
    if (i >= n4) return;
    const float4 x = reinterpret_cast<const float4*>(s)[i];
    uint4 y;
    y.x = f2tf32(x.x); y.y = f2tf32(x.y); y.z = f2tf32(x.z); y.w = f2tf32(x.w);
    reinterpret_cast<uint4*>(d)[i] = y;
}

// ---------------- tf32 GEMM: BM=128, BN=256, 64x64 warp tiles, 3-stage cp.async ----------------
constexpr int ASTR = 36;
constexpr int BSTR = 264;                    // 264 mod 32 = 8 -> frag addr 8qd+g conflict-free
constexpr int A_WORDS = 128 * ASTR;          // 4608
constexpr int B_WORDS = 32 * BSTR;           // 8448
constexpr int STAGE_WORDS = A_WORDS + B_WORDS;   // 13056
constexpr int GEMM_SMEM = 3 * STAGE_WORDS * 4;   // 156,672 B

template<int NN, int KD>
__global__ void __launch_bounds__(256) tgemm_tf32_kernel(
    const uint32_t* __restrict__ A, const uint32_t* __restrict__ B,
    const float* __restrict__ bias, float* __restrict__ C)
{
    extern __shared__ uint32_t smem[];

    const int tid  = threadIdx.x;
    const int lane = tid & 31;
    const int w    = tid >> 5;
    const int g    = lane >> 2;
    const int qd   = lane & 3;
    const int wm   = w >> 2;   // 0..1 (64-row slab)
    const int wn   = w & 3;    // 0..3 (64-col slab)
    const int bm   = blockIdx.y * 128;
    const int bn   = blockIdx.x * 256;

    const int ar = tid >> 1;            // 0..127
    const int ah = (tid & 1) * 16;
    const int br = tid >> 3;            // 0..31 (k row)
    const int bc = tid & 7;

    auto issue = [&](int kt) {
        const int k0 = kt * 32;
        uint32_t* as = smem + (kt % 3) * STAGE_WORDS;
        uint32_t* bs = as + A_WORDS;
        #pragma unroll
        for (int i = 0; i < 4; i++) {
            const uint32_t dst = smem_addr(&as[ar * ASTR + ah + i * 4]);
            CP_ASYNC16(dst, &A[(size_t)(bm + ar) * KD + k0 + ah + i * 4]);
        }
        #pragma unroll
        for (int i = 0; i < 8; i++) {
            const int col = (bc + 8 * i) * 4;
            const uint32_t dst = smem_addr(&bs[br * BSTR + col]);
            CP_ASYNC16(dst, &B[(size_t)(k0 + br) * NN + bn + col]);
        }
        CP_COMMIT();
    };

    float acc[4][8][4] = {};

    issue(0);
    issue(1);

    constexpr int KT = KD / 32;
    for (int kt = 0; kt < KT; kt++) {
        CP_WAIT1();
        __syncthreads();
        if (kt + 2 < KT) issue(kt + 2);

        const uint32_t* as = smem + (kt % 3) * STAGE_WORDS;
        const uint32_t* bs = as + A_WORDS;

        #pragma unroll
        for (int kk = 0; kk < 32; kk += 8) {
            uint32_t af[4][4], bf[8][2];
            #pragma unroll
            for (int mi = 0; mi < 4; mi++) {
                const int r0 = (wm * 64 + mi * 16 + g) * ASTR;
                af[mi][0] = as[r0 + kk + qd];
                af[mi][1] = as[r0 + 8 * ASTR + kk + qd];
                af[mi][2] = as[r0 + kk + 4 + qd];
                af[mi][3] = as[r0 + 8 * ASTR + kk + 4 + qd];
            }
            #pragma unroll
            for (int ni = 0; ni < 8; ni++) {
                const int c0 = wn * 64 + ni * 8 + g;
                bf[ni][0] = bs[(kk + qd) * BSTR + c0];
                bf[ni][1] = bs[(kk + 4 + qd) * BSTR + c0];
            }
            #pragma unroll
            for (int mi = 0; mi < 4; mi++)
                #pragma unroll
                for (int ni = 0; ni < 8; ni++)
                    mma_tf32(acc[mi][ni], af[mi], bf[ni]);
        }
        __syncthreads();
    }

    #pragma unroll
    for (int mi = 0; mi < 4; mi++) {
        const int row = bm + wm * 64 + mi * 16 + g;
        #pragma unroll
        for (int ni = 0; ni < 8; ni++) {
            const int col = bn + wn * 64 + ni * 8 + 2 * qd;
            const float2 bb = *reinterpret_cast<const float2*>(&bias[col]);
            float2 o0, o1;
            o0.x = acc[mi][ni][0] + bb.x; o0.y = acc[mi][ni][1] + bb.y;
            o1.x = acc[mi][ni][2] + bb.x; o1.y = acc[mi][ni][3] + bb.y;
            *reinterpret_cast<float2*>(&C[(size_t)row * NN + col]) = o0;
            *reinterpret_cast<float2*>(&C[(size_t)(row + 8) * NN + col]) = o1;
        }
    }
}

// ---------------- RoPE + split + bf16 hi/lo (q/k) + tf32 (v) ----------------
__global__ void __launch_bounds__(256) rope_split_kernel(
    const float* __restrict__ qkv, const float* __restrict__ cosNK,
    const float* __restrict__ sinNK,
    uint32_t* __restrict__ qhib, uint32_t* __restrict__ qlob,
    uint32_t* __restrict__ khib, uint32_t* __restrict__ klob,
    uint32_t* __restrict__ vtf)
{
    const int idx = blockIdx.x * blockDim.x + threadIdx.x;
    if (idx >= N_TOK * H * WPR) return;
    const int wd = idx % WPR;
    const int h  = (idx / WPR) % H;
    const int n  = idx / (WPR * H);

    const float* base = qkv + (size_t)n * 3 * H * HK;

    float qr[2], kr[2], vv[2];
    #pragma unroll
    for (int e = 0; e < 2; e++) {
        const int kk = 2 * wd + e;
        const float c = cosNK[n * HK + kk];
        const float s = sinNK[n * HK + kk];
        const int off  = h * HK + kk;
        const int krot = (kk < HK / 2) ? kk + HK / 2 : kk - HK / 2;
        const float sg = (kk < HK / 2) ? -1.f : 1.f;
        const int offr = h * HK + krot;
        const float qv  = base[off];
        const float kv  = base[H * HK + off];
        vv[e]           = base[2 * H * HK + off];
        const float qvr = base[offr];
        const float kvr = base[H * HK + offr];
        qr[e] = (qv * c + sg * qvr * s) * SCALE;
        kr[e] = kv * c + sg * kvr * s;
    }

    uint32_t qh[2], ql[2], kh[2], kl[2];
    #pragma unroll
    for (int e = 0; e < 2; e++) {
        qh[e] = bf16bits(qr[e]);
        ql[e] = bf16bits(qr[e] - bf16val(qh[e]));
        kh[e] = bf16bits(kr[e]);
        kl[e] = bf16bits(kr[e] - bf16val(kh[e]));
    }

    const size_t ow = (size_t)h * N_TOK * WPR + (size_t)n * WPR + wd;
    qhib[ow] = (qh[1] << 16) | qh[0];
    qlob[ow] = (ql[1] << 16) | ql[0];
    khib[ow] = (kh[1] << 16) | kh[0];
    klob[ow] = (kl[1] << 16) | kl[0];

    const size_t ov = (size_t)h * N_TOK * HK + (size_t)n * HK + 2 * wd;
    vtf[ov]     = f2tf32(vv[0]);
    vtf[ov + 1] = f2tf32(vv[1]);
}

// ---------------- mma flash attention: Q in regs, cp.async double-buffered K/V ----------------
constexpr int QTQ  = 64;
constexpr int KTK  = 32;
constexpr int QSTR = 44;   // k smem stride (packed bf16x2 words)
constexpr int VSTR = 88;   // v smem stride
constexpr int PST  = 36;   // P stride

constexpr int ATT_SMEM_WORDS =
    2 * KTK * QSTR      // khi double-buffered   2816
    + 2 * KTK * QSTR    // klo                    2816
    + 2 * KTK * VSTR    // v                      5632
    + 4 * 16 * PST      // P                      2304
    + 2 * QTQ + 2;      // rs, re, blk

__global__ void __launch_bounds__(128, 3) attn_mma_kernel(
    const uint32_t* __restrict__ gqhi, const uint32_t* __restrict__ gqlo,
    const uint32_t* __restrict__ gkhi, const uint32_t* __restrict__ gklo,
    const uint32_t* __restrict__ gvtf, const int* __restrict__ cu,
    uint32_t* __restrict__ attn_tf)
{
    extern __shared__ uint32_t sm[];
    uint32_t* khiS = sm;                       // [2][KTK*QSTR]
    uint32_t* kloS = khiS + 2 * KTK * QSTR;
    uint32_t* vS   = kloS + 2 * KTK * QSTR;    // [2][KTK*VSTR]
    uint32_t* pS   = vS + 2 * KTK * VSTR;
    int*      rs   = (int*)(pS + 4 * 16 * PST);
    int*      re   = rs + QTQ;
    int*      blk  = re + QTQ;

    const int h    = blockIdx.y;
    const int q0   = blockIdx.x * QTQ;
    const int tid  = threadIdx.x;
    const int w    = tid >> 5;
    const int lane = tid & 31;
    const int g    = lane >> 2;
    const int qd   = lane & 3;

    if (tid < QTQ) {
        const int n = q0 + tid;
        int lo = 0, hi = N_TOK;
        #pragma unroll
        for (int sgi = 0; sgi < NSEG; sgi++) {
            const int a = cu[sgi], b = cu[sgi + 1];
            if (n >= a && n < b) { lo = a; hi = b; }
        }
        rs[tid] = lo; re[tid] = hi;
    }
    __syncthreads();
    if (tid == 0) {
        int lo = rs[0], hi = re[0];
        #pragma unroll
        for (int r = 1; r < QTQ; r++) { lo = min(lo, rs[r]); hi = max(hi, re[r]); }
        blk[0] = lo; blk[1] = hi;
    }

    int wlo = N_TOK, whi = 0;
    #pragma unroll
    for (int r = 0; r < 16; r++) {
        wlo = min(wlo, rs[w * 16 + r]);
        whi = max(whi, re[w * 16 + r]);
    }
    const int rowA = w * 16 + g, rowB = rowA + 8;
    const int rsA = rs[rowA], reA = re[rowA];
    const int rsB = rs[rowB], reB = re[rowB];

    // Q fragments -> registers (one-time global loads)
    const size_t hb40 = (size_t)h * N_TOK * WPR;
    const size_t hb80 = (size_t)h * N_TOK * HK;
    uint32_t qh[5][4], ql[5][4];
    #pragma unroll
    for (int sl = 0; sl < 5; sl++) {
        const size_t bA = hb40 + (size_t)(q0 + rowA) * WPR + sl * 8;
        const size_t bB = hb40 + (size_t)(q0 + rowB) * WPR + sl * 8;
        qh[sl][0] = gqhi[bA + qd];     qh[sl][1] = gqhi[bB + qd];
        qh[sl][2] = gqhi[bA + 4 + qd]; qh[sl][3] = gqhi[bB + 4 + qd];
        ql[sl][0] = gqlo[bA + qd];     ql[sl][1] = gqlo[bB + qd];
        ql[sl][2] = gqlo[bA + 4 + qd]; ql[sl][3] = gqlo[bB + 4 + qd];
    }
    __syncthreads();
    const int lo = blk[0], hi = blk[1];

    auto stageKV = [&](int kc, int buf) {
        uint32_t* kh_ = khiS + buf * KTK * QSTR;
        uint32_t* kl_ = kloS + buf * KTK * QSTR;
        uint32_t* v_  = vS + buf * KTK * VSTR;
        for (int i = tid; i < KTK * 10; i += 128) {
            const int r = i / 10, c = (i % 10) * 4;
            const int m = kc + r;
            const uint32_t sz = (m < hi) ? 16u : 0u;
            const size_t go = hb40 + (size_t)min(m, hi - 1) * WPR + c;
            CP_ASYNC16Z(smem_addr(&kh_[r * QSTR + c]), &gkhi[go], sz);
            CP_ASYNC16Z(smem_addr(&kl_[r * QSTR + c]), &gklo[go], sz);
        }
        for (int i = tid; i < KTK * 20; i += 128) {
            const int r = i / 20, c = (i % 20) * 4;
            const int m = kc + r;
            const uint32_t sz = (m < hi) ? 16u : 0u;
            const size_t go = hb80 + (size_t)min(m, hi - 1) * HK + c;
            CP_ASYNC16Z(smem_addr(&v_[r * VSTR + c]), &gvtf[go], sz);
        }
        CP_COMMIT();
    };

    float miA = -1e30f, liA = 0.f, miB = -1e30f, liB = 0.f;
    float acc[10][4] = {};
    uint32_t* pw = pS + w * (16 * PST);

    const int T = (hi - lo + KTK - 1) / KTK;
    stageKV(lo, 0);

    for (int t = 0; t < T; t++) {
        const int kc  = lo + t * KTK;
        const int buf = t & 1;
        if (t + 1 < T) { stageKV(kc + KTK, buf ^ 1); CP_WAIT1(); }
        else           { CP_WAIT0(); }
        __syncthreads();

        if (!(kc + KTK <= wlo || kc >= whi)) {
            const uint32_t* kh_ = khiS + buf * KTK * QSTR;
            const uint32_t* kl_ = kloS + buf * KTK * QSTR;
            const uint32_t* v_  = vS + buf * KTK * VSTR;

            float s[4][4] = {};
            #pragma unroll
            for (int sl = 0; sl < 5; sl++) {
                const int base = sl * 8;
                #pragma unroll
                for (int nt = 0; nt < 4; nt++) {
                    const int kr = (nt * 8 + g) * QSTR + base;
                    uint32_t bh[2], bl[2];
                    bh[0] = kh_[kr + qd]; bh[1] = kh_[kr + 4 + qd];
                    bl[0] = kl_[kr + qd]; bl[1] = kl_[kr + 4 + qd];
                    mma_bf16(s[nt], qh[sl], bh);
                    mma_bf16(s[nt], qh[sl], bl);
                    mma_bf16(s[nt], ql[sl], bh);
                }
            }

            float mxA = -1e30f, mxB = -1e30f;
            #pragma unroll
            for (int nt = 0; nt < 4; nt++) {
                const int c0 = kc + nt * 8 + 2 * qd;
                const int c1 = c0 + 1;
                mxA = fmaxf(mxA, fmaxf((c0 >= rsA && c0 < reA) ? s[nt][0] : -1e30f,
                                       (c1 >= rsA && c1 < reA) ? s[nt][1] : -1e30f));
                mxB = fmaxf(mxB, fmaxf((c0 >= rsB && c0 < reB) ? s[nt][2] : -1e30f,
                                       (c1 >= rsB && c1 < reB) ? s[nt][3] : -1e30f));
            }
            #pragma unroll
            for (int off = 1; off <= 2; off <<= 1) {
                mxA = fmaxf(mxA, __shfl_xor_sync(0xffffffffu, mxA, off));
                mxB = fmaxf(mxB, __shfl_xor_sync(0xffffffffu, mxB, off));
            }
            const float nmA = fmaxf(miA, mxA), nmB = fmaxf(miB, mxB);
            const float crA = __expf(miA - nmA), crB = __expf(miB - nmB);
            float sumA = 0.f, sumB = 0.f;
            #pragma unroll
            for (int nt = 0; nt < 4; nt++) {
                const int c0 = kc + nt * 8 + 2 * qd;
                const int c1 = c0 + 1;
                s[nt][0] = (c0 >= rsA && c0 < reA) ? __expf(s[nt][0] - nmA) : 0.f;
                s[nt][1] = (c1 >= rsA && c1 < reA) ? __expf(s[nt][1] - nmA) : 0.f;
                s[nt][2] = (c0 >= rsB && c0 < reB) ? __expf(s[nt][2] - nmB) : 0.f;
                s[nt][3] = (c1 >= rsB && c1 < reB) ? __expf(s[nt][3] - nmB) : 0.f;
                sumA += s[nt][0] + s[nt][1];
                sumB += s[nt][2] + s[nt][3];
            }
            #pragma unroll
            for (int off = 1; off <= 2; off <<= 1) {
                sumA += __shfl_xor_sync(0xffffffffu, sumA, off);
                sumB += __shfl_xor_sync(0xffffffffu, sumB, off);
            }
            liA = liA * crA + sumA; miA = nmA;
            liB = liB * crB + sumB; miB = nmB;

            #pragma unroll
            for (int nt = 0; nt < 10; nt++) {
                acc[nt][0] *= crA; acc[nt][1] *= crA;
                acc[nt][2] *= crB; acc[nt][3] *= crB;
            }

            #pragma unroll
            for (int nt = 0; nt < 4; nt++) {
                const int cb = nt * 8 + 2 * qd;
                uint2 pa, pb;
                pa.x = f2tf32(s[nt][0]); pa.y = f2tf32(s[nt][1]);
                pb.x = f2tf32(s[nt][2]); pb.y = f2tf32(s[nt][3]);
                *reinterpret_cast<uint2*>(&pw[g * PST + cb])       = pa;
                *reinterpret_cast<uint2*>(&pw[(g + 8) * PST + cb]) = pb;
            }
            __syncwarp();

            #pragma unroll
            for (int k8 = 0; k8 < KTK; k8 += 8) {
                uint32_t a[4];
                a[0] = pw[g * PST + k8 + qd];
                a[1] = pw[(g + 8) * PST + k8 + qd];
                a[2] = pw[g * PST + k8 + 4 + qd];
                a[3] = pw[(g + 8) * PST + k8 + 4 + qd];
                #pragma unroll
                for (int nt = 0; nt < 10; nt++) {
                    uint32_t b[2];
                    b[0] = v_[(k8 + qd) * VSTR + nt * 8 + g];
                    b[1] = v_[(k8 + 4 + qd) * VSTR + nt * 8 + g];
                    mma_tf32(acc[nt], a, b);
                }
            }
            __syncwarp();
        }
        __syncthreads();
    }

    const float invA = 1.f / liA, invB = 1.f / liB;
    uint32_t* dA = attn_tf + (size_t)(q0 + rowA) * D + h * HK;
    uint32_t* dB = attn_tf + (size_t)(q0 + rowB) * D + h * HK;
    #pragma unroll
    for (int nt = 0; nt < 10; nt++) {
        const int col = nt * 8 + 2 * qd;
        dA[col]     = f2tf32(acc[nt][0] * invA);
        dA[col + 1] = f2tf32(acc[nt][1] * invA);
        dB[col]     = f2tf32(acc[nt][2] * invB);
        dB[col + 1] = f2tf32(acc[nt][3] * invB);
    }
}

// ---------------- launch ----------------
extern "C" void kernel_launch(void* const* d_in, const int* in_sizes, int n_in,
                              void* d_out, int out_size)
{
    const float* hidden = (const float*)d_in[0];
    const int*   cu     = (const int*)  d_in[1];
    const float* cosNK  = (const float*)d_in[2];
    const float* sinNK  = (const float*)d_in[3];
    const float* qkv_w  = (const float*)d_in[4];
    const float* qkv_b  = (const float*)d_in[5];
    const float* proj_w = (const float*)d_in[6];
    const float* proj_b = (const float*)d_in[7];
    float* out = (float*)d_out;

    float *qkv;
    uint32_t *hidtf, *qkvwtf, *projwtf, *qhib, *qlob, *khib, *klob, *vtf, *attntf;
    cudaGetSymbolAddress((void**)&hidtf,  g_hid_tf);
    cudaGetSymbolAddress((void**)&qkvwtf, g_qkvw_tf);
    cudaGetSymbolAddress((void**)&projwtf,g_projw_tf);
    cudaGetSymbolAddress((void**)&qkv,    g_qkv);
    cudaGetSymbolAddress((void**)&qhib,   g_qhib);
    cudaGetSymbolAddress((void**)&qlob,   g_qlob);
    cudaGetSymbolAddress((void**)&khib,   g_khib);
    cudaGetSymbolAddress((void**)&klob,   g_klob);
    cudaGetSymbolAddress((void**)&vtf,    g_vtf);
    cudaGetSymbolAddress((void**)&attntf, g_attn_tf);

    const size_t attn_smem = ATT_SMEM_WORDS * sizeof(uint32_t);
    static bool attr_done = false;
    if (!attr_done) {
        cudaFuncSetAttribute(tgemm_tf32_kernel<3 * D, D>,
                             cudaFuncAttributeMaxDynamicSharedMemorySize, GEMM_SMEM);
        cudaFuncSetAttribute(tgemm_tf32_kernel<D, D>,
                             cudaFuncAttributeMaxDynamicSharedMemorySize, GEMM_SMEM);
        cudaFuncSetAttribute(attn_mma_kernel,
                             cudaFuncAttributeMaxDynamicSharedMemorySize, (int)attn_smem);
        attr_done = true;
    }

    // 0) converts
    f32_to_tf32_kernel<<<(N_TOK * D / 4 + 255) / 256, 256>>>(hidden, hidtf, N_TOK * D / 4);
    f32_to_tf32_kernel<<<(D * 3 * D / 4 + 255) / 256, 256>>>(qkv_w, qkvwtf, D * 3 * D / 4);
    f32_to_tf32_kernel<<<(D * D / 4 + 255) / 256, 256>>>(proj_w, projwtf, D * D / 4);

    // 1) QKV GEMM + bias  (BN=256 tiles)
    tgemm_tf32_kernel<3 * D, D><<<dim3((3 * D) / 256, N_TOK / 128), 256, GEMM_SMEM>>>(
        hidtf, qkvwtf, qkv_b, qkv);

    // 2) RoPE + split + bf16 hi/lo + tf32 v
    rope_split_kernel<<<(N_TOK * H * WPR + 255) / 256, 256>>>(
        qkv, cosNK, sinNK, qhib, qlob, khib, klob, vtf);

    // 3) mma flash attention (Q-in-regs, double-buffered K/V) -> tf32 output
    attn_mma_kernel<<<dim3(N_TOK / QTQ, H), 128, attn_smem>>>(
        qhib, qlob, khib, klob, vtf, cu, attntf);

    // 4) projection GEMM + bias -> d_out
    tgemm_tf32_kernel<D, D><<<dim3(D / 256, N_TOK / 128), 256, GEMM_SMEM>>>(
        attntf, projwtf, proj_b, out);
}

// round 11
// speedup vs baseline: 1.2174x; 1.0270x over previous
#include <cuda_runtime.h>
#include <cuda_bf16.h>
#include <cstdint>

// Problem constants
constexpr int N_TOK = 3072;
constexpr int D     = 1280;
constexpr int H     = 16;
constexpr int HK    = 80;     // head dim
constexpr int WPR   = HK / 2; // packed bf16 words per row (40)
constexpr int NSEG  = 8;
constexpr float SCALE = 0.111803398874989485f; // 80^-0.5

// ---------------- scratch ----------------
__device__ uint32_t g_hid_tf[N_TOK * D];        // tf32 of hidden
__device__ uint32_t g_qkvw_tf[D * 3 * D];       // tf32 of qkv_w
__device__ uint32_t g_projw_tf[D * D];          // tf32 of proj_w
__device__ float    g_qkv[N_TOK * 3 * D];       // [N][3][H][K] fp32
__device__ uint32_t g_qhib[H * N_TOK * WPR];    // bf16x2 hi of SCALE*rope(q)
__device__ uint32_t g_qlob[H * N_TOK * WPR];
__device__ uint32_t g_khib[H * N_TOK * WPR];
__device__ uint32_t g_klob[H * N_TOK * WPR];
__device__ uint32_t g_vtf[H * N_TOK * HK];      // tf32 v
__device__ uint32_t g_attn_tf[N_TOK * D];       // tf32 attn out [N][H*K]

// ---------------- helpers ----------------
__device__ __forceinline__ uint32_t f2tf32(float x) {
    uint32_t r;
    asm("cvt.rna.tf32.f32 %0, %1;" : "=r"(r) : "f"(x));
    return r;
}
__device__ __forceinline__ void mma_tf32(float c[4], const uint32_t a[4], const uint32_t b[2]) {
    asm volatile(
        "mma.sync.aligned.m16n8k8.row.col.f32.tf32.tf32.f32 "
        "{%0,%1,%2,%3}, {%4,%5,%6,%7}, {%8,%9}, {%0,%1,%2,%3};"
        : "+f"(c[0]), "+f"(c[1]), "+f"(c[2]), "+f"(c[3])
        : "r"(a[0]), "r"(a[1]), "r"(a[2]), "r"(a[3]), "r"(b[0]), "r"(b[1]));
}
__device__ __forceinline__ void mma_bf16(float c[4], const uint32_t a[4], const uint32_t b[2]) {
    asm volatile(
        "mma.sync.aligned.m16n8k16.row.col.f32.bf16.bf16.f32 "
        "{%0,%1,%2,%3}, {%4,%5,%6,%7}, {%8,%9}, {%0,%1,%2,%3};"
        : "+f"(c[0]), "+f"(c[1]), "+f"(c[2]), "+f"(c[3])
        : "r"(a[0]), "r"(a[1]), "r"(a[2]), "r"(a[3]), "r"(b[0]), "r"(b[1]));
}
__device__ __forceinline__ uint32_t bf16bits(float x) {
    const __nv_bfloat16 b = __float2bfloat16(x);
    return (uint32_t)*reinterpret_cast<const uint16_t*>(&b);
}
__device__ __forceinline__ float bf16val(uint32_t bits) {
    const uint16_t u = (uint16_t)bits;
    return __bfloat162float(*reinterpret_cast<const __nv_bfloat16*>(&u));
}
__device__ __forceinline__ uint32_t smem_addr(const void* p) {
    return (uint32_t)__cvta_generic_to_shared(p);
}
#define CP_ASYNC16(dst, src) \
    asm volatile("cp.async.cg.shared.global [%0], [%1], 16;" :: "r"(dst), "l"(src))
#define CP_ASYNC16Z(dst, src, sz) \
    asm volatile("cp.async.cg.shared.global [%0], [%1], 16, %2;" :: "r"(dst), "l"(src), "r"(sz))
#define CP_COMMIT() asm volatile("cp.async.commit_group;")
#define CP_WAIT1()  asm volatile("cp.async.wait_group 1;")
#define CP_WAIT0()  asm volatile("cp.async.wait_group 0;")

// ---------------- merged f32 -> tf32 convert (hidden + qkv_w + proj_w) ----------------
constexpr int CVT_N1 = N_TOK * D / 4;        // hidden float4 count
constexpr int CVT_N2 = D * 3 * D / 4;        // qkv_w
constexpr int CVT_N3 = D * D / 4;            // proj_w
constexpr int CVT_TOT = CVT_N1 + CVT_N2 + CVT_N3;

__global__ void __launch_bounds__(256) convert_all_kernel(
    const float* __restrict__ hid, const float* __restrict__ qw,
    const float* __restrict__ pw,
    uint32_t* __restrict__ hidtf, uint32_t* __restrict__ qwtf,
    uint32_t* __restrict__ pwtf)
{
    const int i = blockIdx.x * blockDim.x + threadIdx.x;
    if (i >= CVT_TOT) return;
    const float* s;
    uint32_t* d;
    int j = i;
    if (j < CVT_N1)            { s = hid; d = hidtf; }
    else if ((j -= CVT_N1) < CVT_N2) { s = qw; d = qwtf; }
    else                       { j -= CVT_N2; s = pw; d = pwtf; }
    const float4 x = reinterpret_cast<const float4*>(s)[j];
    uint4 y;
    y.x = f2tf32(x.x); y.y = f2tf32(x.y); y.z = f2tf32(x.z); y.w = f2tf32(x.w);
    reinterpret_cast<uint4*>(d)[j] = y;
}

// ---------------- tf32 GEMM v128: BM=128, BN=128, 3-stage cp.async (R9 proven) ----------------
constexpr int ASTR = 36;
constexpr int BSTR1 = 136;
constexpr int A_WORDS = 128 * ASTR;              // 4608
constexpr int B_WORDS1 = 32 * BSTR1;             // 4352
constexpr int STAGE1 = A_WORDS + B_WORDS1;       // 8960
constexpr int GEMM_SMEM1 = 3 * STAGE1 * 4;       // 107,520 B

template<int NN, int KD>
__global__ void __launch_bounds__(256) tgemm128_kernel(
    const uint32_t* __restrict__ A, const uint32_t* __restrict__ B,
    const float* __restrict__ bias, float* __restrict__ C)
{
    extern __shared__ uint32_t smem[];

    const int tid  = threadIdx.x;
    const int lane = tid & 31;
    const int w    = tid >> 5;
    const int g    = lane >> 2;
    const int qd   = lane & 3;
    const int wm   = w >> 2;
    const int wn   = w & 3;
    const int bm   = blockIdx.y * 128;
    const int bn   = blockIdx.x * 128;

    const int ar = tid >> 1;
    const int ah = (tid & 1) * 16;
    const int br = tid >> 3;
    const int bc = tid & 7;

    auto issue = [&](int kt) {
        const int k0 = kt * 32;
        uint32_t* as = smem + (kt % 3) * STAGE1;
        uint32_t* bs = as + A_WORDS;
        #pragma unroll
        for (int i = 0; i < 4; i++) {
            const uint32_t dst = smem_addr(&as[ar * ASTR + ah + i * 4]);
            CP_ASYNC16(dst, &A[(size_t)(bm + ar) * KD + k0 + ah + i * 4]);
        }
        #pragma unroll
        for (int i = 0; i < 4; i++) {
            const int col = (bc + 8 * i) * 4;
            const uint32_t dst = smem_addr(&bs[br * BSTR1 + col]);
            CP_ASYNC16(dst, &B[(size_t)(k0 + br) * NN + bn + col]);
        }
        CP_COMMIT();
    };

    float acc[4][4][4] = {};

    issue(0);
    issue(1);

    constexpr int KT = KD / 32;
    for (int kt = 0; kt < KT; kt++) {
        CP_WAIT1();
        __syncthreads();
        if (kt + 2 < KT) issue(kt + 2);

        const uint32_t* as = smem + (kt % 3) * STAGE1;
        const uint32_t* bs = as + A_WORDS;

        #pragma unroll
        for (int kk = 0; kk < 32; kk += 8) {
            uint32_t af[4][4], bf[4][2];
            #pragma unroll
            for (int mi = 0; mi < 4; mi++) {
                const int r0 = (wm * 64 + mi * 16 + g) * ASTR;
                af[mi][0] = as[r0 + kk + qd];
                af[mi][1] = as[r0 + 8 * ASTR + kk + qd];
                af[mi][2] = as[r0 + kk + 4 + qd];
                af[mi][3] = as[r0 + 8 * ASTR + kk + 4 + qd];
            }
            #pragma unroll
            for (int ni = 0; ni < 4; ni++) {
                const int c0 = wn * 32 + ni * 8 + g;
                bf[ni][0] = bs[(kk + qd) * BSTR1 + c0];
                bf[ni][1] = bs[(kk + 4 + qd) * BSTR1 + c0];
            }
            #pragma unroll
            for (int mi = 0; mi < 4; mi++)
                #pragma unroll
                for (int ni = 0; ni < 4; ni++)
                    mma_tf32(acc[mi][ni], af[mi], bf[ni]);
        }
        __syncthreads();
    }

    #pragma unroll
    for (int mi = 0; mi < 4; mi++) {
        const int row = bm + wm * 64 + mi * 16 + g;
        #pragma unroll
        for (int ni = 0; ni < 4; ni++) {
            const int col = bn + wn * 32 + ni * 8 + 2 * qd;
            const float2 bb = *reinterpret_cast<const float2*>(&bias[col]);
            float2 o0, o1;
            o0.x = acc[mi][ni][0] + bb.x; o0.y = acc[mi][ni][1] + bb.y;
            o1.x = acc[mi][ni][2] + bb.x; o1.y = acc[mi][ni][3] + bb.y;
            *reinterpret_cast<float2*>(&C[(size_t)row * NN + col]) = o0;
            *reinterpret_cast<float2*>(&C[(size_t)(row + 8) * NN + col]) = o1;
        }
    }
}

// ---------------- tf32 GEMM v256: BM=128, BN=256 (single-wave proj) ----------------
constexpr int BSTR2 = 264;
constexpr int B_WORDS2 = 32 * BSTR2;             // 8448
constexpr int STAGE2 = A_WORDS + B_WORDS2;       // 13056
constexpr int GEMM_SMEM2 = 3 * STAGE2 * 4;       // 156,672 B

template<int NN, int KD>
__global__ void __launch_bounds__(256) tgemm256_kernel(
    const uint32_t* __restrict__ A, const uint32_t* __restrict__ B,
    const float* __restrict__ bias, float* __restrict__ C)
{
    extern __shared__ uint32_t smem[];

    const int tid  = threadIdx.x;
    const int lane = tid & 31;
    const int w    = tid >> 5;
    const int g    = lane >> 2;
    const int qd   = lane & 3;
    const int wm   = w >> 2;
    const int wn   = w & 3;
    const int bm   = blockIdx.y * 128;
    const int bn   = blockIdx.x * 256;

    const int ar = tid >> 1;
    const int ah = (tid & 1) * 16;
    const int br = tid >> 3;
    const int bc = tid & 7;

    auto issue = [&](int kt) {
        const int k0 = kt * 32;
        uint32_t* as = smem + (kt % 3) * STAGE2;
        uint32_t* bs = as + A_WORDS;
        #pragma unroll
        for (int i = 0; i < 4; i++) {
            const uint32_t dst = smem_addr(&as[ar * ASTR + ah + i * 4]);
            CP_ASYNC16(dst, &A[(size_t)(bm + ar) * KD + k0 + ah + i * 4]);
        }
        #pragma unroll
        for (int i = 0; i < 8; i++) {
            const int col = (bc + 8 * i) * 4;
            const uint32_t dst = smem_addr(&bs[br * BSTR2 + col]);
            CP_ASYNC16(dst, &B[(size_t)(k0 + br) * NN + bn + col]);
        }
        CP_COMMIT();
    };

    float acc[4][8][4] = {};

    issue(0);
    issue(1);

    constexpr int KT = KD / 32;
    for (int kt = 0; kt < KT; kt++) {
        CP_WAIT1();
        __syncthreads();
        if (kt + 2 < KT) issue(kt + 2);

        const uint32_t* as = smem + (kt % 3) * STAGE2;
        const uint32_t* bs = as + A_WORDS;

        #pragma unroll
        for (int kk = 0; kk < 32; kk += 8) {
            uint32_t af[4][4], bf[8][2];
            #pragma unroll
            for (int mi = 0; mi < 4; mi++) {
                const int r0 = (wm * 64 + mi * 16 + g) * ASTR;
                af[mi][0] = as[r0 + kk + qd];
                af[mi][1] = as[r0 + 8 * ASTR + kk + qd];
                af[mi][2] = as[r0 + kk + 4 + qd];
                af[mi][3] = as[r0 + 8 * ASTR + kk + 4 + qd];
            }
            #pragma unroll
            for (int ni = 0; ni < 8; ni++) {
                const int c0 = wn * 64 + ni * 8 + g;
                bf[ni][0] = bs[(kk + qd) * BSTR2 + c0];
                bf[ni][1] = bs[(kk + 4 + qd) * BSTR2 + c0];
            }
            #pragma unroll
            for (int mi = 0; mi < 4; mi++)
                #pragma unroll
                for (int ni = 0; ni < 8; ni++)
                    mma_tf32(acc[mi][ni], af[mi], bf[ni]);
        }
        __syncthreads();
    }

    #pragma unroll
    for (int mi = 0; mi < 4; mi++) {
        const int row = bm + wm * 64 + mi * 16 + g;
        #pragma unroll
        for (int ni = 0; ni < 8; ni++) {
            const int col = bn + wn * 64 + ni * 8 + 2 * qd;
            const float2 bb = *reinterpret_cast<const float2*>(&bias[col]);
            float2 o0, o1;
            o0.x = acc[mi][ni][0] + bb.x; o0.y = acc[mi][ni][1] + bb.y;
            o1.x = acc[mi][ni][2] + bb.x; o1.y = acc[mi][ni][3] + bb.y;
            *reinterpret_cast<float2*>(&C[(size_t)row * NN + col]) = o0;
            *reinterpret_cast<float2*>(&C[(size_t)(row + 8) * NN + col]) = o1;
        }
    }
}

// ---------------- RoPE + split + bf16 hi/lo (q/k) + tf32 (v) ----------------
__global__ void __launch_bounds__(256) rope_split_kernel(
    const float* __restrict__ qkv, const float* __restrict__ cosNK,
    const float* __restrict__ sinNK,
    uint32_t* __restrict__ qhib, uint32_t* __restrict__ qlob,
    uint32_t* __restrict__ khib, uint32_t* __restrict__ klob,
    uint32_t* __restrict__ vtf)
{
    const int idx = blockIdx.x * blockDim.x + threadIdx.x;
    if (idx >= N_TOK * H * WPR) return;
    const int wd = idx % WPR;
    const int h  = (idx / WPR) % H;
    const int n  = idx / (WPR * H);

    const float* base = qkv + (size_t)n * 3 * H * HK;

    float qr[2], kr[2], vv[2];
    #pragma unroll
    for (int e = 0; e < 2; e++) {
        const int kk = 2 * wd + e;
        const float c = cosNK[n * HK + kk];
        const float s = sinNK[n * HK + kk];
        const int off  = h * HK + kk;
        const int krot = (kk < HK / 2) ? kk + HK / 2 : kk - HK / 2;
        const float sg = (kk < HK / 2) ? -1.f : 1.f;
        const int offr = h * HK + krot;
        const float qv  = base[off];
        const float kv  = base[H * HK + off];
        vv[e]           = base[2 * H * HK + off];
        const float qvr = base[offr];
        const float kvr = base[H * HK + offr];
        qr[e] = (qv * c + sg * qvr * s) * SCALE;
        kr[e] = kv * c + sg * kvr * s;
    }

    uint32_t qh[2], ql[2], kh[2], kl[2];
    #pragma unroll
    for (int e = 0; e < 2; e++) {
        qh[e] = bf16bits(qr[e]);
        ql[e] = bf16bits(qr[e] - bf16val(qh[e]));
        kh[e] = bf16bits(kr[e]);
        kl[e] = bf16bits(kr[e] - bf16val(kh[e]));
    }

    const size_t ow = (size_t)h * N_TOK * WPR + (size_t)n * WPR + wd;
    qhib[ow] = (qh[1] << 16) | qh[0];
    qlob[ow] = (ql[1] << 16) | ql[0];
    khib[ow] = (kh[1] << 16) | kh[0];
    klob[ow] = (kl[1] << 16) | kl[0];

    const size_t ov = (size_t)h * N_TOK * HK + (size_t)n * HK + 2 * wd;
    vtf[ov]     = f2tf32(vv[0]);
    vtf[ov + 1] = f2tf32(vv[1]);
}

// ---------------- mma flash attention: Q in regs, cp.async double-buffered K/V ----------------
constexpr int QTQ  = 64;
constexpr int KTK  = 32;
constexpr int QSTR = 44;   // k smem stride (packed bf16x2 words)
constexpr int VSTR = 88;   // v smem stride
constexpr int PST  = 36;   // P stride

constexpr int ATT_SMEM_WORDS =
    2 * KTK * QSTR + 2 * KTK * QSTR + 2 * KTK * VSTR + 4 * 16 * PST + 2 * QTQ + 2;

__global__ void __launch_bounds__(128, 3) attn_mma_kernel(
    const uint32_t* __restrict__ gqhi, const uint32_t* __restrict__ gqlo,
    const uint32_t* __restrict__ gkhi, const uint32_t* __restrict__ gklo,
    const uint32_t* __restrict__ gvtf, const int* __restrict__ cu,
    uint32_t* __restrict__ attn_tf)
{
    extern __shared__ uint32_t sm[];
    uint32_t* khiS = sm;
    uint32_t* kloS = khiS + 2 * KTK * QSTR;
    uint32_t* vS   = kloS + 2 * KTK * QSTR;
    uint32_t* pS   = vS + 2 * KTK * VSTR;
    int*      rs   = (int*)(pS + 4 * 16 * PST);
    int*      re   = rs + QTQ;
    int*      blk  = re + QTQ;

    const int h    = blockIdx.y;
    const int q0   = blockIdx.x * QTQ;
    const int tid  = threadIdx.x;
    const int w    = tid >> 5;
    const int lane = tid & 31;
    const int g    = lane >> 2;
    const int qd   = lane & 3;

    if (tid < QTQ) {
        const int n = q0 + tid;
        int lo = 0, hi = N_TOK;
        #pragma unroll
        for (int sgi = 0; sgi < NSEG; sgi++) {
            const int a = cu[sgi], b = cu[sgi + 1];
            if (n >= a && n < b) { lo = a; hi = b; }
        }
        rs[tid] = lo; re[tid] = hi;
    }
    __syncthreads();
    if (tid == 0) {
        int lo = rs[0], hi = re[0];
        #pragma unroll
        for (int r = 1; r < QTQ; r++) { lo = min(lo, rs[r]); hi = max(hi, re[r]); }
        blk[0] = lo; blk[1] = hi;
    }

    int wlo = N_TOK, whi = 0;
    #pragma unroll
    for (int r = 0; r < 16; r++) {
        wlo = min(wlo, rs[w * 16 + r]);
        whi = max(whi, re[w * 16 + r]);
    }
    const int rowA = w * 16 + g, rowB = rowA + 8;
    const int rsA = rs[rowA], reA = re[rowA];
    const int rsB = rs[rowB], reB = re[rowB];

    const size_t hb40 = (size_t)h * N_TOK * WPR;
    const size_t hb80 = (size_t)h * N_TOK * HK;
    uint32_t qh[5][4], ql[5][4];
    #pragma unroll
    for (int sl = 0; sl < 5; sl++) {
        const size_t bA = hb40 + (size_t)(q0 + rowA) * WPR + sl * 8;
        const size_t bB = hb40 + (size_t)(q0 + rowB) * WPR + sl * 8;
        qh[sl][0] = gqhi[bA + qd];     qh[sl][1] = gqhi[bB + qd];
        qh[sl][2] = gqhi[bA + 4 + qd]; qh[sl][3] = gqhi[bB + 4 + qd];
        ql[sl][0] = gqlo[bA + qd];     ql[sl][1] = gqlo[bB + qd];
        ql[sl][2] = gqlo[bA + 4 + qd]; ql[sl][3] = gqlo[bB + 4 + qd];
    }
    __syncthreads();
    const int lo = blk[0], hi = blk[1];

    auto stageKV = [&](int kc, int buf) {
        uint32_t* kh_ = khiS + buf * KTK * QSTR;
        uint32_t* kl_ = kloS + buf * KTK * QSTR;
        uint32_t* v_  = vS + buf * KTK * VSTR;
        for (int i = tid; i < KTK * 10; i += 128) {
            const int r = i / 10, c = (i % 10) * 4;
            const int m = kc + r;
            const uint32_t sz = (m < hi) ? 16u : 0u;
            const size_t go = hb40 + (size_t)min(m, hi - 1) * WPR + c;
            CP_ASYNC16Z(smem_addr(&kh_[r * QSTR + c]), &gkhi[go], sz);
            CP_ASYNC16Z(smem_addr(&kl_[r * QSTR + c]), &gklo[go], sz);
        }
        for (int i = tid; i < KTK * 20; i += 128) {
            const int r = i / 20, c = (i % 20) * 4;
            const int m = kc + r;
            const uint32_t sz = (m < hi) ? 16u : 0u;
            const size_t go = hb80 + (size_t)min(m, hi - 1) * HK + c;
            CP_ASYNC16Z(smem_addr(&v_[r * VSTR + c]), &gvtf[go], sz);
        }
        CP_COMMIT();
    };

    float miA = -1e30f, liA = 0.f, miB = -1e30f, liB = 0.f;
    float acc[10][4] = {};
    uint32_t* pw = pS + w * (16 * PST);

    const int T = (hi - lo + KTK - 1) / KTK;
    stageKV(lo, 0);

    for (int t = 0; t < T; t++) {
        const int kc  = lo + t * KTK;
        const int buf = t & 1;
        if (t + 1 < T) { stageKV(kc + KTK, buf ^ 1); CP_WAIT1(); }
        else           { CP_WAIT0(); }
        __syncthreads();

        if (!(kc + KTK <= wlo || kc >= whi)) {
            const uint32_t* kh_ = khiS + buf * KTK * QSTR;
            const uint32_t* kl_ = kloS + buf * KTK * QSTR;
            const uint32_t* v_  = vS + buf * KTK * VSTR;

            float s[4][4] = {};
            #pragma unroll
            for (int sl = 0; sl < 5; sl++) {
                const int base = sl * 8;
                #pragma unroll
                for (int nt = 0; nt < 4; nt++) {
                    const int kr = (nt * 8 + g) * QSTR + base;
                    uint32_t bh[2], bl[2];
                    bh[0] = kh_[kr + qd]; bh[1] = kh_[kr + 4 + qd];
                    bl[0] = kl_[kr + qd]; bl[1] = kl_[kr + 4 + qd];
                    mma_bf16(s[nt], qh[sl], bh);
                    mma_bf16(s[nt], qh[sl], bl);
                    mma_bf16(s[nt], ql[sl], bh);
                }
            }

            float mxA = -1e30f, mxB = -1e30f;
            #pragma unroll
            for (int nt = 0; nt < 4; nt++) {
                const int c0 = kc + nt * 8 + 2 * qd;
                const int c1 = c0 + 1;
                mxA = fmaxf(mxA, fmaxf((c0 >= rsA && c0 < reA) ? s[nt][0] : -1e30f,
                                       (c1 >= rsA && c1 < reA) ? s[nt][1] : -1e30f));
                mxB = fmaxf(mxB, fmaxf((c0 >= rsB && c0 < reB) ? s[nt][2] : -1e30f,
                                       (c1 >= rsB && c1 < reB) ? s[nt][3] : -1e30f));
            }
            #pragma unroll
            for (int off = 1; off <= 2; off <<= 1) {
                mxA = fmaxf(mxA, __shfl_xor_sync(0xffffffffu, mxA, off));
                mxB = fmaxf(mxB, __shfl_xor_sync(0xffffffffu, mxB, off));
            }
            const float nmA = fmaxf(miA, mxA), nmB = fmaxf(miB, mxB);
            const float crA = __expf(miA - nmA), crB = __expf(miB - nmB);
            float sumA = 0.f, sumB = 0.f;
            #pragma unroll
            for (int nt = 0; nt < 4; nt++) {
                const int c0 = kc + nt * 8 + 2 * qd;
                const int c1 = c0 + 1;
                s[nt][0] = (c0 >= rsA && c0 < reA) ? __expf(s[nt][0] - nmA) : 0.f;
                s[nt][1] = (c1 >= rsA && c1 < reA) ? __expf(s[nt][1] - nmA) : 0.f;
                s[nt][2] = (c0 >= rsB && c0 < reB) ? __expf(s[nt][2] - nmB) : 0.f;
                s[nt][3] = (c1 >= rsB && c1 < reB) ? __expf(s[nt][3] - nmB) : 0.f;
                sumA += s[nt][0] + s[nt][1];
                sumB += s[nt][2] + s[nt][3];
            }
            #pragma unroll
            for (int off = 1; off <= 2; off <<= 1) {
                sumA += __shfl_xor_sync(0xffffffffu, sumA, off);
                sumB += __shfl_xor_sync(0xffffffffu, sumB, off);
            }
            liA = liA * crA + sumA; miA = nmA;
            liB = liB * crB + sumB; miB = nmB;

            #pragma unroll
            for (int nt = 0; nt < 10; nt++) {
                acc[nt][0] *= crA; acc[nt][1] *= crA;
                acc[nt][2] *= crB; acc[nt][3] *= crB;
            }

            #pragma unroll
            for (int nt = 0; nt < 4; nt++) {
                const int cb = nt * 8 + 2 * qd;
                uint2 pa, pb;
                pa.x = f2tf32(s[nt][0]); pa.y = f2tf32(s[nt][1]);
                pb.x = f2tf32(s[nt][2]); pb.y = f2tf32(s[nt][3]);
                *reinterpret_cast<uint2*>(&pw[g * PST + cb])       = pa;
                *reinterpret_cast<uint2*>(&pw[(g + 8) * PST + cb]) = pb;
            }
            __syncwarp();

            #pragma unroll
            for (int k8 = 0; k8 < KTK; k8 += 8) {
                uint32_t a[4];
                a[0] = pw[g * PST + k8 + qd];
                a[1] = pw[(g + 8) * PST + k8 + qd];
                a[2] = pw[g * PST + k8 + 4 + qd];
                a[3] = pw[(g + 8) * PST + k8 + 4 + qd];
                #pragma unroll
                for (int nt = 0; nt < 10; nt++) {
                    uint32_t b[2];
                    b[0] = v_[(k8 + qd) * VSTR + nt * 8 + g];
                    b[1] = v_[(k8 + 4 + qd) * VSTR + nt * 8 + g];
                    mma_tf32(acc[nt], a, b);
                }
            }
            __syncwarp();
        }
        __syncthreads();
    }

    const float invA = 1.f / liA, invB = 1.f / liB;
    uint32_t* dA = attn_tf + (size_t)(q0 + rowA) * D + h * HK;
    uint32_t* dB = attn_tf + (size_t)(q0 + rowB) * D + h * HK;
    #pragma unroll
    for (int nt = 0; nt < 10; nt++) {
        const int col = nt * 8 + 2 * qd;
        dA[col]     = f2tf32(acc[nt][0] * invA);
        dA[col + 1] = f2tf32(acc[nt][1] * invA);
        dB[col]     = f2tf32(acc[nt][2] * invB);
        dB[col + 1] = f2tf32(acc[nt][3] * invB);
    }
}

// ---------------- launch ----------------
extern "C" void kernel_launch(void* const* d_in, const int* in_sizes, int n_in,
                              void* d_out, int out_size)
{
    const float* hidden = (const float*)d_in[0];
    const int*   cu     = (const int*)  d_in[1];
    const float* cosNK  = (const float*)d_in[2];
    const float* sinNK  = (const float*)d_in[3];
    const float* qkv_w  = (const float*)d_in[4];
    const float* qkv_b  = (const float*)d_in[5];
    const float* proj_w = (const float*)d_in[6];
    const float* proj_b = (const float*)d_in[7];
    float* out = (float*)d_out;

    float *qkv;
    uint32_t *hidtf, *qkvwtf, *projwtf, *qhib, *qlob, *khib, *klob, *vtf, *attntf;
    cudaGetSymbolAddress((void**)&hidtf,  g_hid_tf);
    cudaGetSymbolAddress((void**)&qkvwtf, g_qkvw_tf);
    cudaGetSymbolAddress((void**)&projwtf,g_projw_tf);
    cudaGetSymbolAddress((void**)&qkv,    g_qkv);
    cudaGetSymbolAddress((void**)&qhib,   g_qhib);
    cudaGetSymbolAddress((void**)&qlob,   g_qlob);
    cudaGetSymbolAddress((void**)&khib,   g_khib);
    cudaGetSymbolAddress((void**)&klob,   g_klob);
    cudaGetSymbolAddress((void**)&vtf,    g_vtf);
    cudaGetSymbolAddress((void**)&attntf, g_attn_tf);

    const size_t attn_smem = ATT_SMEM_WORDS * sizeof(uint32_t);
    static bool attr_done = false;
    if (!attr_done) {
        cudaFuncSetAttribute(tgemm128_kernel<3 * D, D>,
                             cudaFuncAttributeMaxDynamicSharedMemorySize, GEMM_SMEM1);
        cudaFuncSetAttribute(tgemm256_kernel<D, D>,
                             cudaFuncAttributeMaxDynamicSharedMemorySize, GEMM_SMEM2);
        cudaFuncSetAttribute(attn_mma_kernel,
                             cudaFuncAttributeMaxDynamicSharedMemorySize, (int)attn_smem);
        attr_done = true;
    }

    // 0) merged converts (hidden + qkv_w + proj_w)
    convert_all_kernel<<<(CVT_TOT + 255) / 256, 256>>>(
        hidden, qkv_w, proj_w, hidtf, qkvwtf, projwtf);

    // 1) QKV GEMM + bias (128x128 tiles — measured best for this shape)
    tgemm128_kernel<3 * D, D><<<dim3((3 * D) / 128, N_TOK / 128), 256, GEMM_SMEM1>>>(
        hidtf, qkvwtf, qkv_b, qkv);

    // 2) RoPE + split + bf16 hi/lo + tf32 v
    rope_split_kernel<<<(N_TOK * H * WPR + 255) / 256, 256>>>(
        qkv, cosNK, sinNK, qhib, qlob, khib, klob, vtf);

    // 3) mma flash attention (Q-in-regs, double-buffered K/V) -> tf32 output
    attn_mma_kernel<<<dim3(N_TOK / QTQ, H), 128, attn_smem>>>(
        qhib, qlob, khib, klob, vtf, cu, attntf);

    // 4) projection GEMM + bias (128x256 tiles — single wave) -> d_out
    tgemm256_kernel<D, D><<<dim3(D / 256, N_TOK / 128), 256, GEMM_SMEM2>>>(
        attntf, projwtf, proj_b, out);
}

// round 12
// speedup vs baseline: 1.2717x; 1.0446x over previous
#include <cuda_runtime.h>
#include <cuda_bf16.h>
#include <cstdint>

// Problem constants
constexpr int N_TOK = 3072;
constexpr int D     = 1280;
constexpr int H     = 16;
constexpr int HK    = 80;     // head dim
constexpr int WPR   = HK / 2; // packed bf16 words per row (40)
constexpr int NSEG  = 8;
constexpr float SCALE = 0.111803398874989485f; // 80^-0.5

// ---------------- scratch ----------------
__device__ uint32_t g_hid_tf[N_TOK * D];        // tf32 of hidden
__device__ uint32_t g_qkvw_tf[D * 3 * D];       // tf32 of qkv_w
__device__ uint32_t g_projw_tf[D * D];          // tf32 of proj_w
__device__ float    g_qkv[N_TOK * 3 * D];       // [N][3][H][K] fp32
__device__ uint32_t g_qhib[H * N_TOK * WPR];    // bf16x2 hi of SCALE*rope(q)
__device__ uint32_t g_qlob[H * N_TOK * WPR];
__device__ uint32_t g_khib[H * N_TOK * WPR];
__device__ uint32_t g_klob[H * N_TOK * WPR];
__device__ uint32_t g_vtf[H * N_TOK * HK];      // tf32 v
__device__ uint32_t g_attn_tf[N_TOK * D];       // tf32 attn out [N][H*K]

// ---------------- helpers ----------------
__device__ __forceinline__ uint32_t f2tf32(float x) {
    uint32_t r;
    asm("cvt.rna.tf32.f32 %0, %1;" : "=r"(r) : "f"(x));
    return r;
}
__device__ __forceinline__ void mma_tf32(float c[4], const uint32_t a[4], const uint32_t b[2]) {
    asm volatile(
        "mma.sync.aligned.m16n8k8.row.col.f32.tf32.tf32.f32 "
        "{%0,%1,%2,%3}, {%4,%5,%6,%7}, {%8,%9}, {%0,%1,%2,%3};"
        : "+f"(c[0]), "+f"(c[1]), "+f"(c[2]), "+f"(c[3])
        : "r"(a[0]), "r"(a[1]), "r"(a[2]), "r"(a[3]), "r"(b[0]), "r"(b[1]));
}
__device__ __forceinline__ void mma_bf16(float c[4], const uint32_t a[4], const uint32_t b[2]) {
    asm volatile(
        "mma.sync.aligned.m16n8k16.row.col.f32.bf16.bf16.f32 "
        "{%0,%1,%2,%3}, {%4,%5,%6,%7}, {%8,%9}, {%0,%1,%2,%3};"
        : "+f"(c[0]), "+f"(c[1]), "+f"(c[2]), "+f"(c[3])
        : "r"(a[0]), "r"(a[1]), "r"(a[2]), "r"(a[3]), "r"(b[0]), "r"(b[1]));
}
__device__ __forceinline__ uint32_t bf16bits(float x) {
    const __nv_bfloat16 b = __float2bfloat16(x);
    return (uint32_t)*reinterpret_cast<const uint16_t*>(&b);
}
__device__ __forceinline__ float bf16val(uint32_t bits) {
    const uint16_t u = (uint16_t)bits;
    return __bfloat162float(*reinterpret_cast<const __nv_bfloat16*>(&u));
}
__device__ __forceinline__ uint32_t smem_addr(const void* p) {
    return (uint32_t)__cvta_generic_to_shared(p);
}
#define CP_ASYNC16(dst, src) \
    asm volatile("cp.async.cg.shared.global [%0], [%1], 16;" :: "r"(dst), "l"(src))
#define CP_ASYNC16Z(dst, src, sz) \
    asm volatile("cp.async.cg.shared.global [%0], [%1], 16, %2;" :: "r"(dst), "l"(src), "r"(sz))
#define CP_COMMIT() asm volatile("cp.async.commit_group;")
#define CP_WAIT1()  asm volatile("cp.async.wait_group 1;")
#define CP_WAIT0()  asm volatile("cp.async.wait_group 0;")

// ---------------- merged f32 -> tf32 convert (hidden + qkv_w + proj_w) ----------------
constexpr int CVT_N1 = N_TOK * D / 4;
constexpr int CVT_N2 = D * 3 * D / 4;
constexpr int CVT_N3 = D * D / 4;
constexpr int CVT_TOT = CVT_N1 + CVT_N2 + CVT_N3;

__global__ void __launch_bounds__(256) convert_all_kernel(
    const float* __restrict__ hid, const float* __restrict__ qw,
    const float* __restrict__ pw,
    uint32_t* __restrict__ hidtf, uint32_t* __restrict__ qwtf,
    uint32_t* __restrict__ pwtf)
{
    const int i = blockIdx.x * blockDim.x + threadIdx.x;
    if (i >= CVT_TOT) return;
    const float* s;
    uint32_t* d;
    int j = i;
    if (j < CVT_N1)            { s = hid; d = hidtf; }
    else if ((j -= CVT_N1) < CVT_N2) { s = qw; d = qwtf; }
    else                       { j -= CVT_N2; s = pw; d = pwtf; }
    const float4 x = reinterpret_cast<const float4*>(s)[j];
    uint4 y;
    y.x = f2tf32(x.x); y.y = f2tf32(x.y); y.z = f2tf32(x.z); y.w = f2tf32(x.w);
    reinterpret_cast<uint4*>(d)[j] = y;
}

// ---------------- tf32 GEMM v128: BM=128, BN=128, 3-stage cp.async ----------------
constexpr int ASTR = 36;
constexpr int BSTR1 = 136;
constexpr int A_WORDS = 128 * ASTR;
constexpr int B_WORDS1 = 32 * BSTR1;
constexpr int STAGE1 = A_WORDS + B_WORDS1;
constexpr int GEMM_SMEM1 = 3 * STAGE1 * 4;

template<int NN, int KD>
__global__ void __launch_bounds__(256) tgemm128_kernel(
    const uint32_t* __restrict__ A, const uint32_t* __restrict__ B,
    const float* __restrict__ bias, float* __restrict__ C)
{
    extern __shared__ uint32_t smem[];

    const int tid  = threadIdx.x;
    const int lane = tid & 31;
    const int w    = tid >> 5;
    const int g    = lane >> 2;
    const int qd   = lane & 3;
    const int wm   = w >> 2;
    const int wn   = w & 3;
    const int bm   = blockIdx.y * 128;
    const int bn   = blockIdx.x * 128;

    const int ar = tid >> 1;
    const int ah = (tid & 1) * 16;
    const int br = tid >> 3;
    const int bc = tid & 7;

    auto issue = [&](int kt) {
        const int k0 = kt * 32;
        uint32_t* as = smem + (kt % 3) * STAGE1;
        uint32_t* bs = as + A_WORDS;
        #pragma unroll
        for (int i = 0; i < 4; i++) {
            const uint32_t dst = smem_addr(&as[ar * ASTR + ah + i * 4]);
            CP_ASYNC16(dst, &A[(size_t)(bm + ar) * KD + k0 + ah + i * 4]);
        }
        #pragma unroll
        for (int i = 0; i < 4; i++) {
            const int col = (bc + 8 * i) * 4;
            const uint32_t dst = smem_addr(&bs[br * BSTR1 + col]);
            CP_ASYNC16(dst, &B[(size_t)(k0 + br) * NN + bn + col]);
        }
        CP_COMMIT();
    };

    float acc[4][4][4] = {};

    issue(0);
    issue(1);

    constexpr int KT = KD / 32;
    for (int kt = 0; kt < KT; kt++) {
        CP_WAIT1();
        __syncthreads();
        if (kt + 2 < KT) issue(kt + 2);

        const uint32_t* as = smem + (kt % 3) * STAGE1;
        const uint32_t* bs = as + A_WORDS;

        #pragma unroll
        for (int kk = 0; kk < 32; kk += 8) {
            uint32_t af[4][4], bf[4][2];
            #pragma unroll
            for (int mi = 0; mi < 4; mi++) {
                const int r0 = (wm * 64 + mi * 16 + g) * ASTR;
                af[mi][0] = as[r0 + kk + qd];
                af[mi][1] = as[r0 + 8 * ASTR + kk + qd];
                af[mi][2] = as[r0 + kk + 4 + qd];
                af[mi][3] = as[r0 + 8 * ASTR + kk + 4 + qd];
            }
            #pragma unroll
            for (int ni = 0; ni < 4; ni++) {
                const int c0 = wn * 32 + ni * 8 + g;
                bf[ni][0] = bs[(kk + qd) * BSTR1 + c0];
                bf[ni][1] = bs[(kk + 4 + qd) * BSTR1 + c0];
            }
            #pragma unroll
            for (int mi = 0; mi < 4; mi++)
                #pragma unroll
                for (int ni = 0; ni < 4; ni++)
                    mma_tf32(acc[mi][ni], af[mi], bf[ni]);
        }
        __syncthreads();
    }

    #pragma unroll
    for (int mi = 0; mi < 4; mi++) {
        const int row = bm + wm * 64 + mi * 16 + g;
        #pragma unroll
        for (int ni = 0; ni < 4; ni++) {
            const int col = bn + wn * 32 + ni * 8 + 2 * qd;
            const float2 bb = *reinterpret_cast<const float2*>(&bias[col]);
            float2 o0, o1;
            o0.x = acc[mi][ni][0] + bb.x; o0.y = acc[mi][ni][1] + bb.y;
            o1.x = acc[mi][ni][2] + bb.x; o1.y = acc[mi][ni][3] + bb.y;
            *reinterpret_cast<float2*>(&C[(size_t)row * NN + col]) = o0;
            *reinterpret_cast<float2*>(&C[(size_t)(row + 8) * NN + col]) = o1;
        }
    }
}

// ---------------- tf32 GEMM v256: BM=128, BN=256 (single-wave proj) ----------------
constexpr int BSTR2 = 264;
constexpr int B_WORDS2 = 32 * BSTR2;
constexpr int STAGE2 = A_WORDS + B_WORDS2;
constexpr int GEMM_SMEM2 = 3 * STAGE2 * 4;

template<int NN, int KD>
__global__ void __launch_bounds__(256) tgemm256_kernel(
    const uint32_t* __restrict__ A, const uint32_t* __restrict__ B,
    const float* __restrict__ bias, float* __restrict__ C)
{
    extern __shared__ uint32_t smem[];

    const int tid  = threadIdx.x;
    const int lane = tid & 31;
    const int w    = tid >> 5;
    const int g    = lane >> 2;
    const int qd   = lane & 3;
    const int wm   = w >> 2;
    const int wn   = w & 3;
    const int bm   = blockIdx.y * 128;
    const int bn   = blockIdx.x * 256;

    const int ar = tid >> 1;
    const int ah = (tid & 1) * 16;
    const int br = tid >> 3;
    const int bc = tid & 7;

    auto issue = [&](int kt) {
        const int k0 = kt * 32;
        uint32_t* as = smem + (kt % 3) * STAGE2;
        uint32_t* bs = as + A_WORDS;
        #pragma unroll
        for (int i = 0; i < 4; i++) {
            const uint32_t dst = smem_addr(&as[ar * ASTR + ah + i * 4]);
            CP_ASYNC16(dst, &A[(size_t)(bm + ar) * KD + k0 + ah + i * 4]);
        }
        #pragma unroll
        for (int i = 0; i < 8; i++) {
            const int col = (bc + 8 * i) * 4;
            const uint32_t dst = smem_addr(&bs[br * BSTR2 + col]);
            CP_ASYNC16(dst, &B[(size_t)(k0 + br) * NN + bn + col]);
        }
        CP_COMMIT();
    };

    float acc[4][8][4] = {};

    issue(0);
    issue(1);

    constexpr int KT = KD / 32;
    for (int kt = 0; kt < KT; kt++) {
        CP_WAIT1();
        __syncthreads();
        if (kt + 2 < KT) issue(kt + 2);

        const uint32_t* as = smem + (kt % 3) * STAGE2;
        const uint32_t* bs = as + A_WORDS;

        #pragma unroll
        for (int kk = 0; kk < 32; kk += 8) {
            uint32_t af[4][4], bf[8][2];
            #pragma unroll
            for (int mi = 0; mi < 4; mi++) {
                const int r0 = (wm * 64 + mi * 16 + g) * ASTR;
                af[mi][0] = as[r0 + kk + qd];
                af[mi][1] = as[r0 + 8 * ASTR + kk + qd];
                af[mi][2] = as[r0 + kk + 4 + qd];
                af[mi][3] = as[r0 + 8 * ASTR + kk + 4 + qd];
            }
            #pragma unroll
            for (int ni = 0; ni < 8; ni++) {
                const int c0 = wn * 64 + ni * 8 + g;
                bf[ni][0] = bs[(kk + qd) * BSTR2 + c0];
                bf[ni][1] = bs[(kk + 4 + qd) * BSTR2 + c0];
            }
            #pragma unroll
            for (int mi = 0; mi < 4; mi++)
                #pragma unroll
                for (int ni = 0; ni < 8; ni++)
                    mma_tf32(acc[mi][ni], af[mi], bf[ni]);
        }
        __syncthreads();
    }

    #pragma unroll
    for (int mi = 0; mi < 4; mi++) {
        const int row = bm + wm * 64 + mi * 16 + g;
        #pragma unroll
        for (int ni = 0; ni < 8; ni++) {
            const int col = bn + wn * 64 + ni * 8 + 2 * qd;
            const float2 bb = *reinterpret_cast<const float2*>(&bias[col]);
            float2 o0, o1;
            o0.x = acc[mi][ni][0] + bb.x; o0.y = acc[mi][ni][1] + bb.y;
            o1.x = acc[mi][ni][2] + bb.x; o1.y = acc[mi][ni][3] + bb.y;
            *reinterpret_cast<float2*>(&C[(size_t)row * NN + col]) = o0;
            *reinterpret_cast<float2*>(&C[(size_t)(row + 8) * NN + col]) = o1;
        }
    }
}

// ---------------- RoPE + split + bf16 hi/lo (q/k) + tf32 (v) ----------------
__global__ void __launch_bounds__(256) rope_split_kernel(
    const float* __restrict__ qkv, const float* __restrict__ cosNK,
    const float* __restrict__ sinNK,
    uint32_t* __restrict__ qhib, uint32_t* __restrict__ qlob,
    uint32_t* __restrict__ khib, uint32_t* __restrict__ klob,
    uint32_t* __restrict__ vtf)
{
    const int idx = blockIdx.x * blockDim.x + threadIdx.x;
    if (idx >= N_TOK * H * WPR) return;
    const int wd = idx % WPR;
    const int h  = (idx / WPR) % H;
    const int n  = idx / (WPR * H);

    const float* base = qkv + (size_t)n * 3 * H * HK;

    float qr[2], kr[2], vv[2];
    #pragma unroll
    for (int e = 0; e < 2; e++) {
        const int kk = 2 * wd + e;
        const float c = cosNK[n * HK + kk];
        const float s = sinNK[n * HK + kk];
        const int off  = h * HK + kk;
        const int krot = (kk < HK / 2) ? kk + HK / 2 : kk - HK / 2;
        const float sg = (kk < HK / 2) ? -1.f : 1.f;
        const int offr = h * HK + krot;
        const float qv  = base[off];
        const float kv  = base[H * HK + off];
        vv[e]           = base[2 * H * HK + off];
        const float qvr = base[offr];
        const float kvr = base[H * HK + offr];
        qr[e] = (qv * c + sg * qvr * s) * SCALE;
        kr[e] = kv * c + sg * kvr * s;
    }

    uint32_t qh[2], ql[2], kh[2], kl[2];
    #pragma unroll
    for (int e = 0; e < 2; e++) {
        qh[e] = bf16bits(qr[e]);
        ql[e] = bf16bits(qr[e] - bf16val(qh[e]));
        kh[e] = bf16bits(kr[e]);
        kl[e] = bf16bits(kr[e] - bf16val(kh[e]));
    }

    const size_t ow = (size_t)h * N_TOK * WPR + (size_t)n * WPR + wd;
    qhib[ow] = (qh[1] << 16) | qh[0];
    qlob[ow] = (ql[1] << 16) | ql[0];
    khib[ow] = (kh[1] << 16) | kh[0];
    klob[ow] = (kl[1] << 16) | kl[0];

    const size_t ov = (size_t)h * N_TOK * HK + (size_t)n * HK + 2 * wd;
    vtf[ov]     = f2tf32(vv[0]);
    vtf[ov + 1] = f2tf32(vv[1]);
}

// ---------------- mma flash attention: KTK=64, Q in regs, cp.async double-buffered ----------------
constexpr int QTQ  = 64;
constexpr int KTK  = 64;
constexpr int QSTR = 44;   // k smem stride (packed bf16x2 words)
constexpr int VSTR = 88;   // v smem stride
constexpr int PST  = 68;   // P stride (>=64 cols; g*68 mod 32 = 4g -> conflict-free)

constexpr int ATT_SMEM_WORDS =
    2 * KTK * QSTR      // khi double-buffered   5632
    + 2 * KTK * QSTR    // klo                    5632
    + 2 * KTK * VSTR    // v                     11264
    + 4 * 16 * PST      // P                      4352
    + 2 * QTQ + 2;      // rs, re, blk

__global__ void __launch_bounds__(128, 2) attn_mma_kernel(
    const uint32_t* __restrict__ gqhi, const uint32_t* __restrict__ gqlo,
    const uint32_t* __restrict__ gkhi, const uint32_t* __restrict__ gklo,
    const uint32_t* __restrict__ gvtf, const int* __restrict__ cu,
    uint32_t* __restrict__ attn_tf)
{
    extern __shared__ uint32_t sm[];
    uint32_t* khiS = sm;
    uint32_t* kloS = khiS + 2 * KTK * QSTR;
    uint32_t* vS   = kloS + 2 * KTK * QSTR;
    uint32_t* pS   = vS + 2 * KTK * VSTR;
    int*      rs   = (int*)(pS + 4 * 16 * PST);
    int*      re   = rs + QTQ;
    int*      blk  = re + QTQ;

    const int h    = blockIdx.y;
    const int q0   = blockIdx.x * QTQ;
    const int tid  = threadIdx.x;
    const int w    = tid >> 5;
    const int lane = tid & 31;
    const int g    = lane >> 2;
    const int qd   = lane & 3;

    if (tid < QTQ) {
        const int n = q0 + tid;
        int lo = 0, hi = N_TOK;
        #pragma unroll
        for (int sgi = 0; sgi < NSEG; sgi++) {
            const int a = cu[sgi], b = cu[sgi + 1];
            if (n >= a && n < b) { lo = a; hi = b; }
        }
        rs[tid] = lo; re[tid] = hi;
    }
    __syncthreads();
    if (tid == 0) {
        int lo = rs[0], hi = re[0];
        #pragma unroll
        for (int r = 1; r < QTQ; r++) { lo = min(lo, rs[r]); hi = max(hi, re[r]); }
        blk[0] = lo; blk[1] = hi;
    }

    int wlo = N_TOK, whi = 0;
    #pragma unroll
    for (int r = 0; r < 16; r++) {
        wlo = min(wlo, rs[w * 16 + r]);
        whi = max(whi, re[w * 16 + r]);
    }
    const int rowA = w * 16 + g, rowB = rowA + 8;
    const int rsA = rs[rowA], reA = re[rowA];
    const int rsB = rs[rowB], reB = re[rowB];

    const size_t hb40 = (size_t)h * N_TOK * WPR;
    const size_t hb80 = (size_t)h * N_TOK * HK;
    uint32_t qh[5][4], ql[5][4];
    #pragma unroll
    for (int sl = 0; sl < 5; sl++) {
        const size_t bA = hb40 + (size_t)(q0 + rowA) * WPR + sl * 8;
        const size_t bB = hb40 + (size_t)(q0 + rowB) * WPR + sl * 8;
        qh[sl][0] = gqhi[bA + qd];     qh[sl][1] = gqhi[bB + qd];
        qh[sl][2] = gqhi[bA + 4 + qd]; qh[sl][3] = gqhi[bB + 4 + qd];
        ql[sl][0] = gqlo[bA + qd];     ql[sl][1] = gqlo[bB + qd];
        ql[sl][2] = gqlo[bA + 4 + qd]; ql[sl][3] = gqlo[bB + 4 + qd];
    }
    __syncthreads();
    const int lo = blk[0], hi = blk[1];

    auto stageKV = [&](int kc, int buf) {
        uint32_t* kh_ = khiS + buf * KTK * QSTR;
        uint32_t* kl_ = kloS + buf * KTK * QSTR;
        uint32_t* v_  = vS + buf * KTK * VSTR;
        #pragma unroll
        for (int it = 0; it < 5; it++) {              // KTK*10 = 640 = 5*128
            const int i = it * 128 + tid;
            const int r = i / 10, c = (i % 10) * 4;
            const int m = kc + r;
            const uint32_t sz = (m < hi) ? 16u : 0u;
            const size_t go = hb40 + (size_t)min(m, hi - 1) * WPR + c;
            CP_ASYNC16Z(smem_addr(&kh_[r * QSTR + c]), &gkhi[go], sz);
            CP_ASYNC16Z(smem_addr(&kl_[r * QSTR + c]), &gklo[go], sz);
        }
        #pragma unroll
        for (int it = 0; it < 10; it++) {             // KTK*20 = 1280 = 10*128
            const int i = it * 128 + tid;
            const int r = i / 20, c = (i % 20) * 4;
            const int m = kc + r;
            const uint32_t sz = (m < hi) ? 16u : 0u;
            const size_t go = hb80 + (size_t)min(m, hi - 1) * HK + c;
            CP_ASYNC16Z(smem_addr(&v_[r * VSTR + c]), &gvtf[go], sz);
        }
        CP_COMMIT();
    };

    float miA = -1e30f, liA = 0.f, miB = -1e30f, liB = 0.f;
    float acc[10][4] = {};
    uint32_t* pw = pS + w * (16 * PST);

    const int T = (hi - lo + KTK - 1) / KTK;
    stageKV(lo, 0);

    for (int t = 0; t < T; t++) {
        const int kc  = lo + t * KTK;
        const int buf = t & 1;
        if (t + 1 < T) { stageKV(kc + KTK, buf ^ 1); CP_WAIT1(); }
        else           { CP_WAIT0(); }
        __syncthreads();

        if (!(kc + KTK <= wlo || kc >= whi)) {
            const uint32_t* kh_ = khiS + buf * KTK * QSTR;
            const uint32_t* kl_ = kloS + buf * KTK * QSTR;
            const uint32_t* v_  = vS + buf * KTK * VSTR;

            // ---- S = Q K^T (3x bf16 hi/lo), 16x64 strip per warp ----
            float s[8][4] = {};
            #pragma unroll
            for (int sl = 0; sl < 5; sl++) {
                const int base = sl * 8;
                #pragma unroll
                for (int nt = 0; nt < 8; nt++) {
                    const int kr = (nt * 8 + g) * QSTR + base;
                    uint32_t bh[2], bl[2];
                    bh[0] = kh_[kr + qd]; bh[1] = kh_[kr + 4 + qd];
                    bl[0] = kl_[kr + qd]; bl[1] = kl_[kr + 4 + qd];
                    mma_bf16(s[nt], qh[sl], bh);
                    mma_bf16(s[nt], qh[sl], bl);
                    mma_bf16(s[nt], ql[sl], bh);
                }
            }

            // ---- register softmax over 64 keys ----
            float mxA = -1e30f, mxB = -1e30f;
            #pragma unroll
            for (int nt = 0; nt < 8; nt++) {
                const int c0 = kc + nt * 8 + 2 * qd;
                const int c1 = c0 + 1;
                mxA = fmaxf(mxA, fmaxf((c0 >= rsA && c0 < reA) ? s[nt][0] : -1e30f,
                                       (c1 >= rsA && c1 < reA) ? s[nt][1] : -1e30f));
                mxB = fmaxf(mxB, fmaxf((c0 >= rsB && c0 < reB) ? s[nt][2] : -1e30f,
                                       (c1 >= rsB && c1 < reB) ? s[nt][3] : -1e30f));
            }
            #pragma unroll
            for (int off = 1; off <= 2; off <<= 1) {
                mxA = fmaxf(mxA, __shfl_xor_sync(0xffffffffu, mxA, off));
                mxB = fmaxf(mxB, __shfl_xor_sync(0xffffffffu, mxB, off));
            }
            const float nmA = fmaxf(miA, mxA), nmB = fmaxf(miB, mxB);
            const float crA = __expf(miA - nmA), crB = __expf(miB - nmB);
            float sumA = 0.f, sumB = 0.f;
            #pragma unroll
            for (int nt = 0; nt < 8; nt++) {
                const int c0 = kc + nt * 8 + 2 * qd;
                const int c1 = c0 + 1;
                s[nt][0] = (c0 >= rsA && c0 < reA) ? __expf(s[nt][0] - nmA) : 0.f;
                s[nt][1] = (c1 >= rsA && c1 < reA) ? __expf(s[nt][1] - nmA) : 0.f;
                s[nt][2] = (c0 >= rsB && c0 < reB) ? __expf(s[nt][2] - nmB) : 0.f;
                s[nt][3] = (c1 >= rsB && c1 < reB) ? __expf(s[nt][3] - nmB) : 0.f;
                sumA += s[nt][0] + s[nt][1];
                sumB += s[nt][2] + s[nt][3];
            }
            #pragma unroll
            for (int off = 1; off <= 2; off <<= 1) {
                sumA += __shfl_xor_sync(0xffffffffu, sumA, off);
                sumB += __shfl_xor_sync(0xffffffffu, sumB, off);
            }
            liA = liA * crA + sumA; miA = nmA;
            liB = liB * crB + sumB; miB = nmB;

            #pragma unroll
            for (int nt = 0; nt < 10; nt++) {
                acc[nt][0] *= crA; acc[nt][1] *= crA;
                acc[nt][2] *= crB; acc[nt][3] *= crB;
            }

            // ---- P -> warp-private smem (tf32), then PV (tf32) ----
            #pragma unroll
            for (int nt = 0; nt < 8; nt++) {
                const int cb = nt * 8 + 2 * qd;
                uint2 pa, pb;
                pa.x = f2tf32(s[nt][0]); pa.y = f2tf32(s[nt][1]);
                pb.x = f2tf32(s[nt][2]); pb.y = f2tf32(s[nt][3]);
                *reinterpret_cast<uint2*>(&pw[g * PST + cb])       = pa;
                *reinterpret_cast<uint2*>(&pw[(g + 8) * PST + cb]) = pb;
            }
            __syncwarp();

            #pragma unroll
            for (int k8 = 0; k8 < KTK; k8 += 8) {
                uint32_t a[4];
                a[0] = pw[g * PST + k8 + qd];
                a[1] = pw[(g + 8) * PST + k8 + qd];
                a[2] = pw[g * PST + k8 + 4 + qd];
                a[3] = pw[(g + 8) * PST + k8 + 4 + qd];
                #pragma unroll
                for (int nt = 0; nt < 10; nt++) {
                    uint32_t b[2];
                    b[0] = v_[(k8 + qd) * VSTR + nt * 8 + g];
                    b[1] = v_[(k8 + 4 + qd) * VSTR + nt * 8 + g];
                    mma_tf32(acc[nt], a, b);
                }
            }
            __syncwarp();
        }
        __syncthreads();
    }

    const float invA = 1.f / liA, invB = 1.f / liB;
    uint32_t* dA = attn_tf + (size_t)(q0 + rowA) * D + h * HK;
    uint32_t* dB = attn_tf + (size_t)(q0 + rowB) * D + h * HK;
    #pragma unroll
    for (int nt = 0; nt < 10; nt++) {
        const int col = nt * 8 + 2 * qd;
        dA[col]     = f2tf32(acc[nt][0] * invA);
        dA[col + 1] = f2tf32(acc[nt][1] * invA);
        dB[col]     = f2tf32(acc[nt][2] * invB);
        dB[col + 1] = f2tf32(acc[nt][3] * invB);
    }
}

// ---------------- launch ----------------
extern "C" void kernel_launch(void* const* d_in, const int* in_sizes, int n_in,
                              void* d_out, int out_size)
{
    const float* hidden = (const float*)d_in[0];
    const int*   cu     = (const int*)  d_in[1];
    const float* cosNK  = (const float*)d_in[2];
    const float* sinNK  = (const float*)d_in[3];
    const float* qkv_w  = (const float*)d_in[4];
    const float* qkv_b  = (const float*)d_in[5];
    const float* proj_w = (const float*)d_in[6];
    const float* proj_b = (const float*)d_in[7];
    float* out = (float*)d_out;

    float *qkv;
    uint32_t *hidtf, *qkvwtf, *projwtf, *qhib, *qlob, *khib, *klob, *vtf, *attntf;
    cudaGetSymbolAddress((void**)&hidtf,  g_hid_tf);
    cudaGetSymbolAddress((void**)&qkvwtf, g_qkvw_tf);
    cudaGetSymbolAddress((void**)&projwtf,g_projw_tf);
    cudaGetSymbolAddress((void**)&qkv,    g_qkv);
    cudaGetSymbolAddress((void**)&qhib,   g_qhib);
    cudaGetSymbolAddress((void**)&qlob,   g_qlob);
    cudaGetSymbolAddress((void**)&khib,   g_khib);
    cudaGetSymbolAddress((void**)&klob,   g_klob);
    cudaGetSymbolAddress((void**)&vtf,    g_vtf);
    cudaGetSymbolAddress((void**)&attntf, g_attn_tf);

    const size_t attn_smem = ATT_SMEM_WORDS * sizeof(uint32_t);
    static bool attr_done = false;
    if (!attr_done) {
        cudaFuncSetAttribute(tgemm128_kernel<3 * D, D>,
                             cudaFuncAttributeMaxDynamicSharedMemorySize, GEMM_SMEM1);
        cudaFuncSetAttribute(tgemm256_kernel<D, D>,
                             cudaFuncAttributeMaxDynamicSharedMemorySize, GEMM_SMEM2);
        cudaFuncSetAttribute(attn_mma_kernel,
                             cudaFuncAttributeMaxDynamicSharedMemorySize, (int)attn_smem);
        attr_done = true;
    }

    // 0) merged converts
    convert_all_kernel<<<(CVT_TOT + 255) / 256, 256>>>(
        hidden, qkv_w, proj_w, hidtf, qkvwtf, projwtf);

    // 1) QKV GEMM + bias
    tgemm128_kernel<3 * D, D><<<dim3((3 * D) / 128, N_TOK / 128), 256, GEMM_SMEM1>>>(
        hidtf, qkvwtf, qkv_b, qkv);

    // 2) RoPE + split
    rope_split_kernel<<<(N_TOK * H * WPR + 255) / 256, 256>>>(
        qkv, cosNK, sinNK, qhib, qlob, khib, klob, vtf);

    // 3) attention (KTK=64)
    attn_mma_kernel<<<dim3(N_TOK / QTQ, H), 128, attn_smem>>>(
        qhib, qlob, khib, klob, vtf, cu, attntf);

    // 4) projection GEMM + bias -> d_out
    tgemm256_kernel<D, D><<<dim3(D / 256, N_TOK / 128), 256, GEMM_SMEM2>>>(
        attntf, projwtf, proj_b, out);
}

// round 13
// speedup vs baseline: 1.2729x; 1.0009x over previous
#include <cuda_runtime.h>
#include <cuda_bf16.h>
#include <cstdint>

// Problem constants
constexpr int N_TOK = 3072;
constexpr int D     = 1280;
constexpr int H     = 16;
constexpr int HK    = 80;     // head dim
constexpr int WPR   = HK / 2; // packed bf16 words per row (40)
constexpr int NSEG  = 8;
constexpr float SCALE = 0.111803398874989485f; // 80^-0.5

// ---------------- scratch ----------------
__device__ uint32_t g_hid_tf[N_TOK * D];        // tf32 of hidden
__device__ uint32_t g_qkvw_tf[D * 3 * D];       // tf32 of qkv_w
__device__ uint32_t g_projw_tf[D * D];          // tf32 of proj_w
__device__ float    g_qkv[N_TOK * 3 * D];       // [N][3][H][K] fp32
__device__ uint32_t g_qhib[H * N_TOK * WPR];    // bf16x2 hi of SCALE*rope(q)
__device__ uint32_t g_qlob[H * N_TOK * WPR];
__device__ uint32_t g_khib[H * N_TOK * WPR];
__device__ uint32_t g_klob[H * N_TOK * WPR];
__device__ uint32_t g_vtf[H * N_TOK * HK];      // tf32 v
__device__ uint32_t g_attn_tf[N_TOK * D];       // tf32 attn out [N][H*K]

// ---------------- helpers ----------------
__device__ __forceinline__ uint32_t f2tf32(float x) {
    uint32_t r;
    asm("cvt.rna.tf32.f32 %0, %1;" : "=r"(r) : "f"(x));
    return r;
}
__device__ __forceinline__ void mma_tf32(float c[4], const uint32_t a[4], const uint32_t b[2]) {
    asm volatile(
        "mma.sync.aligned.m16n8k8.row.col.f32.tf32.tf32.f32 "
        "{%0,%1,%2,%3}, {%4,%5,%6,%7}, {%8,%9}, {%0,%1,%2,%3};"
        : "+f"(c[0]), "+f"(c[1]), "+f"(c[2]), "+f"(c[3])
        : "r"(a[0]), "r"(a[1]), "r"(a[2]), "r"(a[3]), "r"(b[0]), "r"(b[1]));
}
__device__ __forceinline__ void mma_bf16(float c[4], const uint32_t a[4], const uint32_t b[2]) {
    asm volatile(
        "mma.sync.aligned.m16n8k16.row.col.f32.bf16.bf16.f32 "
        "{%0,%1,%2,%3}, {%4,%5,%6,%7}, {%8,%9}, {%0,%1,%2,%3};"
        : "+f"(c[0]), "+f"(c[1]), "+f"(c[2]), "+f"(c[3])
        : "r"(a[0]), "r"(a[1]), "r"(a[2]), "r"(a[3]), "r"(b[0]), "r"(b[1]));
}
__device__ __forceinline__ uint32_t bf16bits(float x) {
    const __nv_bfloat16 b = __float2bfloat16(x);
    return (uint32_t)*reinterpret_cast<const uint16_t*>(&b);
}
__device__ __forceinline__ float bf16val(uint32_t bits) {
    const uint16_t u = (uint16_t)bits;
    return __bfloat162float(*reinterpret_cast<const __nv_bfloat16*>(&u));
}
__device__ __forceinline__ uint32_t smem_addr(const void* p) {
    return (uint32_t)__cvta_generic_to_shared(p);
}
#define CP_ASYNC16(dst, src) \
    asm volatile("cp.async.cg.shared.global [%0], [%1], 16;" :: "r"(dst), "l"(src))
#define CP_ASYNC16Z(dst, src, sz) \
    asm volatile("cp.async.cg.shared.global [%0], [%1], 16, %2;" :: "r"(dst), "l"(src), "r"(sz))
#define CP_COMMIT() asm volatile("cp.async.commit_group;")
#define CP_WAIT1()  asm volatile("cp.async.wait_group 1;")
#define CP_WAIT0()  asm volatile("cp.async.wait_group 0;")

// ---------------- merged f32 -> tf32 convert (hidden + qkv_w + proj_w) ----------------
constexpr int CVT_N1 = N_TOK * D / 4;
constexpr int CVT_N2 = D * 3 * D / 4;
constexpr int CVT_N3 = D * D / 4;
constexpr int CVT_TOT = CVT_N1 + CVT_N2 + CVT_N3;

__global__ void __launch_bounds__(256) convert_all_kernel(
    const float* __restrict__ hid, const float* __restrict__ qw,
    const float* __restrict__ pw,
    uint32_t* __restrict__ hidtf, uint32_t* __restrict__ qwtf,
    uint32_t* __restrict__ pwtf)
{
    const int i = blockIdx.x * blockDim.x + threadIdx.x;
    if (i >= CVT_TOT) return;
    const float* s;
    uint32_t* d;
    int j = i;
    if (j < CVT_N1)            { s = hid; d = hidtf; }
    else if ((j -= CVT_N1) < CVT_N2) { s = qw; d = qwtf; }
    else                       { j -= CVT_N2; s = pw; d = pwtf; }
    const float4 x = reinterpret_cast<const float4*>(s)[j];
    uint4 y;
    y.x = f2tf32(x.x); y.y = f2tf32(x.y); y.z = f2tf32(x.z); y.w = f2tf32(x.w);
    reinterpret_cast<uint4*>(d)[j] = y;
}

// ---------------- tf32 GEMM v128: BM=128, BN=128, 3-stage cp.async ----------------
constexpr int ASTR = 36;
constexpr int BSTR1 = 136;
constexpr int A_WORDS = 128 * ASTR;
constexpr int B_WORDS1 = 32 * BSTR1;
constexpr int STAGE1 = A_WORDS + B_WORDS1;
constexpr int GEMM_SMEM1 = 3 * STAGE1 * 4;

template<int NN, int KD>
__global__ void __launch_bounds__(256) tgemm128_kernel(
    const uint32_t* __restrict__ A, const uint32_t* __restrict__ B,
    const float* __restrict__ bias, float* __restrict__ C)
{
    extern __shared__ uint32_t smem[];

    const int tid  = threadIdx.x;
    const int lane = tid & 31;
    const int w    = tid >> 5;
    const int g    = lane >> 2;
    const int qd   = lane & 3;
    const int wm   = w >> 2;
    const int wn   = w & 3;
    const int bm   = blockIdx.y * 128;
    const int bn   = blockIdx.x * 128;

    const int ar = tid >> 1;
    const int ah = (tid & 1) * 16;
    const int br = tid >> 3;
    const int bc = tid & 7;

    auto issue = [&](int kt) {
        const int k0 = kt * 32;
        uint32_t* as = smem + (kt % 3) * STAGE1;
        uint32_t* bs = as + A_WORDS;
        #pragma unroll
        for (int i = 0; i < 4; i++) {
            const uint32_t dst = smem_addr(&as[ar * ASTR + ah + i * 4]);
            CP_ASYNC16(dst, &A[(size_t)(bm + ar) * KD + k0 + ah + i * 4]);
        }
        #pragma unroll
        for (int i = 0; i < 4; i++) {
            const int col = (bc + 8 * i) * 4;
            const uint32_t dst = smem_addr(&bs[br * BSTR1 + col]);
            CP_ASYNC16(dst, &B[(size_t)(k0 + br) * NN + bn + col]);
        }
        CP_COMMIT();
    };

    float acc[4][4][4] = {};

    issue(0);
    issue(1);

    constexpr int KT = KD / 32;
    for (int kt = 0; kt < KT; kt++) {
        CP_WAIT1();
        __syncthreads();
        if (kt + 2 < KT) issue(kt + 2);

        const uint32_t* as = smem + (kt % 3) * STAGE1;
        const uint32_t* bs = as + A_WORDS;

        #pragma unroll
        for (int kk = 0; kk < 32; kk += 8) {
            uint32_t af[4][4], bf[4][2];
            #pragma unroll
            for (int mi = 0; mi < 4; mi++) {
                const int r0 = (wm * 64 + mi * 16 + g) * ASTR;
                af[mi][0] = as[r0 + kk + qd];
                af[mi][1] = as[r0 + 8 * ASTR + kk + qd];
                af[mi][2] = as[r0 + kk + 4 + qd];
                af[mi][3] = as[r0 + 8 * ASTR + kk + 4 + qd];
            }
            #pragma unroll
            for (int ni = 0; ni < 4; ni++) {
                const int c0 = wn * 32 + ni * 8 + g;
                bf[ni][0] = bs[(kk + qd) * BSTR1 + c0];
                bf[ni][1] = bs[(kk + 4 + qd) * BSTR1 + c0];
            }
            #pragma unroll
            for (int mi = 0; mi < 4; mi++)
                #pragma unroll
                for (int ni = 0; ni < 4; ni++)
                    mma_tf32(acc[mi][ni], af[mi], bf[ni]);
        }
        __syncthreads();
    }

    #pragma unroll
    for (int mi = 0; mi < 4; mi++) {
        const int row = bm + wm * 64 + mi * 16 + g;
        #pragma unroll
        for (int ni = 0; ni < 4; ni++) {
            const int col = bn + wn * 32 + ni * 8 + 2 * qd;
            const float2 bb = *reinterpret_cast<const float2*>(&bias[col]);
            float2 o0, o1;
            o0.x = acc[mi][ni][0] + bb.x; o0.y = acc[mi][ni][1] + bb.y;
            o1.x = acc[mi][ni][2] + bb.x; o1.y = acc[mi][ni][3] + bb.y;
            *reinterpret_cast<float2*>(&C[(size_t)row * NN + col]) = o0;
            *reinterpret_cast<float2*>(&C[(size_t)(row + 8) * NN + col]) = o1;
        }
    }
}

// ---------------- tf32 GEMM v256: BM=128, BN=256 (single-wave proj) ----------------
constexpr int BSTR2 = 264;
constexpr int B_WORDS2 = 32 * BSTR2;
constexpr int STAGE2 = A_WORDS + B_WORDS2;
constexpr int GEMM_SMEM2 = 3 * STAGE2 * 4;

template<int NN, int KD>
__global__ void __launch_bounds__(256) tgemm256_kernel(
    const uint32_t* __restrict__ A, const uint32_t* __restrict__ B,
    const float* __restrict__ bias, float* __restrict__ C)
{
    extern __shared__ uint32_t smem[];

    const int tid  = threadIdx.x;
    const int lane = tid & 31;
    const int w    = tid >> 5;
    const int g    = lane >> 2;
    const int qd   = lane & 3;
    const int wm   = w >> 2;
    const int wn   = w & 3;
    const int bm   = blockIdx.y * 128;
    const int bn   = blockIdx.x * 256;

    const int ar = tid >> 1;
    const int ah = (tid & 1) * 16;
    const int br = tid >> 3;
    const int bc = tid & 7;

    auto issue = [&](int kt) {
        const int k0 = kt * 32;
        uint32_t* as = smem + (kt % 3) * STAGE2;
        uint32_t* bs = as + A_WORDS;
        #pragma unroll
        for (int i = 0; i < 4; i++) {
            const uint32_t dst = smem_addr(&as[ar * ASTR + ah + i * 4]);
            CP_ASYNC16(dst, &A[(size_t)(bm + ar) * KD + k0 + ah + i * 4]);
        }
        #pragma unroll
        for (int i = 0; i < 8; i++) {
            const int col = (bc + 8 * i) * 4;
            const uint32_t dst = smem_addr(&bs[br * BSTR2 + col]);
            CP_ASYNC16(dst, &B[(size_t)(k0 + br) * NN + bn + col]);
        }
        CP_COMMIT();
    };

    float acc[4][8][4] = {};

    issue(0);
    issue(1);

    constexpr int KT = KD / 32;
    for (int kt = 0; kt < KT; kt++) {
        CP_WAIT1();
        __syncthreads();
        if (kt + 2 < KT) issue(kt + 2);

        const uint32_t* as = smem + (kt % 3) * STAGE2;
        const uint32_t* bs = as + A_WORDS;

        #pragma unroll
        for (int kk = 0; kk < 32; kk += 8) {
            uint32_t af[4][4], bf[8][2];
            #pragma unroll
            for (int mi = 0; mi < 4; mi++) {
                const int r0 = (wm * 64 + mi * 16 + g) * ASTR;
                af[mi][0] = as[r0 + kk + qd];
                af[mi][1] = as[r0 + 8 * ASTR + kk + qd];
                af[mi][2] = as[r0 + kk + 4 + qd];
                af[mi][3] = as[r0 + 8 * ASTR + kk + 4 + qd];
            }
            #pragma unroll
            for (int ni = 0; ni < 8; ni++) {
                const int c0 = wn * 64 + ni * 8 + g;
                bf[ni][0] = bs[(kk + qd) * BSTR2 + c0];
                bf[ni][1] = bs[(kk + 4 + qd) * BSTR2 + c0];
            }
            #pragma unroll
            for (int mi = 0; mi < 4; mi++)
                #pragma unroll
                for (int ni = 0; ni < 8; ni++)
                    mma_tf32(acc[mi][ni], af[mi], bf[ni]);
        }
        __syncthreads();
    }

    #pragma unroll
    for (int mi = 0; mi < 4; mi++) {
        const int row = bm + wm * 64 + mi * 16 + g;
        #pragma unroll
        for (int ni = 0; ni < 8; ni++) {
            const int col = bn + wn * 64 + ni * 8 + 2 * qd;
            const float2 bb = *reinterpret_cast<const float2*>(&bias[col]);
            float2 o0, o1;
            o0.x = acc[mi][ni][0] + bb.x; o0.y = acc[mi][ni][1] + bb.y;
            o1.x = acc[mi][ni][2] + bb.x; o1.y = acc[mi][ni][3] + bb.y;
            *reinterpret_cast<float2*>(&C[(size_t)row * NN + col]) = o0;
            *reinterpret_cast<float2*>(&C[(size_t)(row + 8) * NN + col]) = o1;
        }
    }
}

// ---------------- RoPE + split + bf16 hi/lo (q/k) + tf32 (v) ----------------
__global__ void __launch_bounds__(256) rope_split_kernel(
    const float* __restrict__ qkv, const float* __restrict__ cosNK,
    const float* __restrict__ sinNK,
    uint32_t* __restrict__ qhib, uint32_t* __restrict__ qlob,
    uint32_t* __restrict__ khib, uint32_t* __restrict__ klob,
    uint32_t* __restrict__ vtf)
{
    const int idx = blockIdx.x * blockDim.x + threadIdx.x;
    if (idx >= N_TOK * H * WPR) return;
    const int wd = idx % WPR;
    const int h  = (idx / WPR) % H;
    const int n  = idx / (WPR * H);

    const float* base = qkv + (size_t)n * 3 * H * HK;

    float qr[2], kr[2], vv[2];
    #pragma unroll
    for (int e = 0; e < 2; e++) {
        const int kk = 2 * wd + e;
        const float c = cosNK[n * HK + kk];
        const float s = sinNK[n * HK + kk];
        const int off  = h * HK + kk;
        const int krot = (kk < HK / 2) ? kk + HK / 2 : kk - HK / 2;
        const float sg = (kk < HK / 2) ? -1.f : 1.f;
        const int offr = h * HK + krot;
        const float qv  = base[off];
        const float kv  = base[H * HK + off];
        vv[e]           = base[2 * H * HK + off];
        const float qvr = base[offr];
        const float kvr = base[H * HK + offr];
        qr[e] = (qv * c + sg * qvr * s) * SCALE;
        kr[e] = kv * c + sg * kvr * s;
    }

    uint32_t qh[2], ql[2], kh[2], kl[2];
    #pragma unroll
    for (int e = 0; e < 2; e++) {
        qh[e] = bf16bits(qr[e]);
        ql[e] = bf16bits(qr[e] - bf16val(qh[e]));
        kh[e] = bf16bits(kr[e]);
        kl[e] = bf16bits(kr[e] - bf16val(kh[e]));
    }

    const size_t ow = (size_t)h * N_TOK * WPR + (size_t)n * WPR + wd;
    qhib[ow] = (qh[1] << 16) | qh[0];
    qlob[ow] = (ql[1] << 16) | ql[0];
    khib[ow] = (kh[1] << 16) | kh[0];
    klob[ow] = (kl[1] << 16) | kl[0];

    const size_t ov = (size_t)h * N_TOK * HK + (size_t)n * HK + 2 * wd;
    vtf[ov]     = f2tf32(vv[0]);
    vtf[ov + 1] = f2tf32(vv[1]);
}

// ---------------- mma flash attention: KTK=64 + interior-tile fast path ----------------
constexpr int QTQ  = 64;
constexpr int KTK  = 64;
constexpr int QSTR = 44;   // k smem stride (packed bf16x2 words)
constexpr int VSTR = 88;   // v smem stride
constexpr int PST  = 68;   // P stride

constexpr int ATT_SMEM_WORDS =
    2 * KTK * QSTR + 2 * KTK * QSTR + 2 * KTK * VSTR + 4 * 16 * PST + 2 * QTQ + 2;

__global__ void __launch_bounds__(128, 2) attn_mma_kernel(
    const uint32_t* __restrict__ gqhi, const uint32_t* __restrict__ gqlo,
    const uint32_t* __restrict__ gkhi, const uint32_t* __restrict__ gklo,
    const uint32_t* __restrict__ gvtf, const int* __restrict__ cu,
    uint32_t* __restrict__ attn_tf)
{
    extern __shared__ uint32_t sm[];
    uint32_t* khiS = sm;
    uint32_t* kloS = khiS + 2 * KTK * QSTR;
    uint32_t* vS   = kloS + 2 * KTK * QSTR;
    uint32_t* pS   = vS + 2 * KTK * VSTR;
    int*      rs   = (int*)(pS + 4 * 16 * PST);
    int*      re   = rs + QTQ;
    int*      blk  = re + QTQ;

    const int h    = blockIdx.y;
    const int q0   = blockIdx.x * QTQ;
    const int tid  = threadIdx.x;
    const int w    = tid >> 5;
    const int lane = tid & 31;
    const int g    = lane >> 2;
    const int qd   = lane & 3;

    if (tid < QTQ) {
        const int n = q0 + tid;
        int lo = 0, hi = N_TOK;
        #pragma unroll
        for (int sgi = 0; sgi < NSEG; sgi++) {
            const int a = cu[sgi], b = cu[sgi + 1];
            if (n >= a && n < b) { lo = a; hi = b; }
        }
        rs[tid] = lo; re[tid] = hi;
    }
    __syncthreads();
    if (tid == 0) {
        int lo = rs[0], hi = re[0];
        #pragma unroll
        for (int r = 1; r < QTQ; r++) { lo = min(lo, rs[r]); hi = max(hi, re[r]); }
        blk[0] = lo; blk[1] = hi;
    }

    // per-warp bounds: union (wlo/whi) for skip; intersection (wrs_max/wre_min) for fast path
    int wlo = N_TOK, whi = 0, wrs_max = 0, wre_min = N_TOK;
    #pragma unroll
    for (int r = 0; r < 16; r++) {
        const int a = rs[w * 16 + r], b = re[w * 16 + r];
        wlo = min(wlo, a); whi = max(whi, b);
        wrs_max = max(wrs_max, a); wre_min = min(wre_min, b);
    }
    const int rowA = w * 16 + g, rowB = rowA + 8;
    const int rsA = rs[rowA], reA = re[rowA];
    const int rsB = rs[rowB], reB = re[rowB];

    const size_t hb40 = (size_t)h * N_TOK * WPR;
    const size_t hb80 = (size_t)h * N_TOK * HK;
    uint32_t qh[5][4], ql[5][4];
    #pragma unroll
    for (int sl = 0; sl < 5; sl++) {
        const size_t bA = hb40 + (size_t)(q0 + rowA) * WPR + sl * 8;
        const size_t bB = hb40 + (size_t)(q0 + rowB) * WPR + sl * 8;
        qh[sl][0] = gqhi[bA + qd];     qh[sl][1] = gqhi[bB + qd];
        qh[sl][2] = gqhi[bA + 4 + qd]; qh[sl][3] = gqhi[bB + 4 + qd];
        ql[sl][0] = gqlo[bA + qd];     ql[sl][1] = gqlo[bB + qd];
        ql[sl][2] = gqlo[bA + 4 + qd]; ql[sl][3] = gqlo[bB + 4 + qd];
    }
    __syncthreads();
    const int lo = blk[0], hi = blk[1];

    auto stageKV = [&](int kc, int buf) {
        uint32_t* kh_ = khiS + buf * KTK * QSTR;
        uint32_t* kl_ = kloS + buf * KTK * QSTR;
        uint32_t* v_  = vS + buf * KTK * VSTR;
        #pragma unroll
        for (int it = 0; it < 5; it++) {
            const int i = it * 128 + tid;
            const int r = i / 10, c = (i % 10) * 4;
            const int m = kc + r;
            const uint32_t sz = (m < hi) ? 16u : 0u;
            const size_t go = hb40 + (size_t)min(m, hi - 1) * WPR + c;
            CP_ASYNC16Z(smem_addr(&kh_[r * QSTR + c]), &gkhi[go], sz);
            CP_ASYNC16Z(smem_addr(&kl_[r * QSTR + c]), &gklo[go], sz);
        }
        #pragma unroll
        for (int it = 0; it < 10; it++) {
            const int i = it * 128 + tid;
            const int r = i / 20, c = (i % 20) * 4;
            const int m = kc + r;
            const uint32_t sz = (m < hi) ? 16u : 0u;
            const size_t go = hb80 + (size_t)min(m, hi - 1) * HK + c;
            CP_ASYNC16Z(smem_addr(&v_[r * VSTR + c]), &gvtf[go], sz);
        }
        CP_COMMIT();
    };

    float miA = -1e30f, liA = 0.f, miB = -1e30f, liB = 0.f;
    float acc[10][4] = {};
    uint32_t* pw = pS + w * (16 * PST);

    const int T = (hi - lo + KTK - 1) / KTK;
    stageKV(lo, 0);

    for (int t = 0; t < T; t++) {
        const int kc  = lo + t * KTK;
        const int buf = t & 1;
        if (t + 1 < T) { stageKV(kc + KTK, buf ^ 1); CP_WAIT1(); }
        else           { CP_WAIT0(); }
        __syncthreads();

        if (!(kc + KTK <= wlo || kc >= whi)) {
            const uint32_t* kh_ = khiS + buf * KTK * QSTR;
            const uint32_t* kl_ = kloS + buf * KTK * QSTR;
            const uint32_t* v_  = vS + buf * KTK * VSTR;

            // ---- S = Q K^T (3x bf16 hi/lo), 16x64 strip per warp ----
            float s[8][4] = {};
            #pragma unroll
            for (int sl = 0; sl < 5; sl++) {
                const int base = sl * 8;
                #pragma unroll
                for (int nt = 0; nt < 8; nt++) {
                    const int kr = (nt * 8 + g) * QSTR + base;
                    uint32_t bh[2], bl[2];
                    bh[0] = kh_[kr + qd]; bh[1] = kh_[kr + 4 + qd];
                    bl[0] = kl_[kr + qd]; bl[1] = kl_[kr + 4 + qd];
                    mma_bf16(s[nt], qh[sl], bh);
                    mma_bf16(s[nt], qh[sl], bl);
                    mma_bf16(s[nt], ql[sl], bh);
                }
            }

            // ---- softmax: fast path for interior tiles, masked path at boundaries ----
            float mxA = -1e30f, mxB = -1e30f, sumA = 0.f, sumB = 0.f;
            float nmA, nmB, crA, crB;
            const bool full = (kc >= wrs_max) && (kc + KTK <= wre_min);
            if (full) {
                #pragma unroll
                for (int nt = 0; nt < 8; nt++) {
                    mxA = fmaxf(mxA, fmaxf(s[nt][0], s[nt][1]));
                    mxB = fmaxf(mxB, fmaxf(s[nt][2], s[nt][3]));
                }
                #pragma unroll
                for (int off = 1; off <= 2; off <<= 1) {
                    mxA = fmaxf(mxA, __shfl_xor_sync(0xffffffffu, mxA, off));
                    mxB = fmaxf(mxB, __shfl_xor_sync(0xffffffffu, mxB, off));
                }
                nmA = fmaxf(miA, mxA); nmB = fmaxf(miB, mxB);
                crA = __expf(miA - nmA); crB = __expf(miB - nmB);
                #pragma unroll
                for (int nt = 0; nt < 8; nt++) {
                    s[nt][0] = __expf(s[nt][0] - nmA);
                    s[nt][1] = __expf(s[nt][1] - nmA);
                    s[nt][2] = __expf(s[nt][2] - nmB);
                    s[nt][3] = __expf(s[nt][3] - nmB);
                    sumA += s[nt][0] + s[nt][1];
                    sumB += s[nt][2] + s[nt][3];
                }
            } else {
                #pragma unroll
                for (int nt = 0; nt < 8; nt++) {
                    const int c0 = kc + nt * 8 + 2 * qd;
                    const int c1 = c0 + 1;
                    mxA = fmaxf(mxA, fmaxf((c0 >= rsA && c0 < reA) ? s[nt][0] : -1e30f,
                                           (c1 >= rsA && c1 < reA) ? s[nt][1] : -1e30f));
                    mxB = fmaxf(mxB, fmaxf((c0 >= rsB && c0 < reB) ? s[nt][2] : -1e30f,
                                           (c1 >= rsB && c1 < reB) ? s[nt][3] : -1e30f));
                }
                #pragma unroll
                for (int off = 1; off <= 2; off <<= 1) {
                    mxA = fmaxf(mxA, __shfl_xor_sync(0xffffffffu, mxA, off));
                    mxB = fmaxf(mxB, __shfl_xor_sync(0xffffffffu, mxB, off));
                }
                nmA = fmaxf(miA, mxA); nmB = fmaxf(miB, mxB);
                crA = __expf(miA - nmA); crB = __expf(miB - nmB);
                #pragma unroll
                for (int nt = 0; nt < 8; nt++) {
                    const int c0 = kc + nt * 8 + 2 * qd;
                    const int c1 = c0 + 1;
                    s[nt][0] = (c0 >= rsA && c0 < reA) ? __expf(s[nt][0] - nmA) : 0.f;
                    s[nt][1] = (c1 >= rsA && c1 < reA) ? __expf(s[nt][1] - nmA) : 0.f;
                    s[nt][2] = (c0 >= rsB && c0 < reB) ? __expf(s[nt][2] - nmB) : 0.f;
                    s[nt][3] = (c1 >= rsB && c1 < reB) ? __expf(s[nt][3] - nmB) : 0.f;
                    sumA += s[nt][0] + s[nt][1];
                    sumB += s[nt][2] + s[nt][3];
                }
            }
            #pragma unroll
            for (int off = 1; off <= 2; off <<= 1) {
                sumA += __shfl_xor_sync(0xffffffffu, sumA, off);
                sumB += __shfl_xor_sync(0xffffffffu, sumB, off);
            }
            liA = liA * crA + sumA; miA = nmA;
            liB = liB * crB + sumB; miB = nmB;

            #pragma unroll
            for (int nt = 0; nt < 10; nt++) {
                acc[nt][0] *= crA; acc[nt][1] *= crA;
                acc[nt][2] *= crB; acc[nt][3] *= crB;
            }

            // ---- P -> warp-private smem (tf32), then PV (tf32) ----
            #pragma unroll
            for (int nt = 0; nt < 8; nt++) {
                const int cb = nt * 8 + 2 * qd;
                uint2 pa, pb;
                pa.x = f2tf32(s[nt][0]); pa.y = f2tf32(s[nt][1]);
                pb.x = f2tf32(s[nt][2]); pb.y = f2tf32(s[nt][3]);
                *reinterpret_cast<uint2*>(&pw[g * PST + cb])       = pa;
                *reinterpret_cast<uint2*>(&pw[(g + 8) * PST + cb]) = pb;
            }
            __syncwarp();

            #pragma unroll
            for (int k8 = 0; k8 < KTK; k8 += 8) {
                uint32_t a[4];
                a[0] = pw[g * PST + k8 + qd];
                a[1] = pw[(g + 8) * PST + k8 + qd];
                a[2] = pw[g * PST + k8 + 4 + qd];
                a[3] = pw[(g + 8) * PST + k8 + 4 + qd];
                #pragma unroll
                for (int nt = 0; nt < 10; nt++) {
                    uint32_t b[2];
                    b[0] = v_[(k8 + qd) * VSTR + nt * 8 + g];
                    b[1] = v_[(k8 + 4 + qd) * VSTR + nt * 8 + g];
                    mma_tf32(acc[nt], a, b);
                }
            }
            __syncwarp();
        }
        __syncthreads();
    }

    const float invA = 1.f / liA, invB = 1.f / liB;
    uint32_t* dA = attn_tf + (size_t)(q0 + rowA) * D + h * HK;
    uint32_t* dB = attn_tf + (size_t)(q0 + rowB) * D + h * HK;
    #pragma unroll
    for (int nt = 0; nt < 10; nt++) {
        const int col = nt * 8 + 2 * qd;
        dA[col]     = f2tf32(acc[nt][0] * invA);
        dA[col + 1] = f2tf32(acc[nt][1] * invA);
        dB[col]     = f2tf32(acc[nt][2] * invB);
        dB[col + 1] = f2tf32(acc[nt][3] * invB);
    }
}

// ---------------- launch ----------------
extern "C" void kernel_launch(void* const* d_in, const int* in_sizes, int n_in,
                              void* d_out, int out_size)
{
    const float* hidden = (const float*)d_in[0];
    const int*   cu     = (const int*)  d_in[1];
    const float* cosNK  = (const float*)d_in[2];
    const float* sinNK  = (const float*)d_in[3];
    const float* qkv_w  = (const float*)d_in[4];
    const float* qkv_b  = (const float*)d_in[5];
    const float* proj_w = (const float*)d_in[6];
    const float* proj_b = (const float*)d_in[7];
    float* out = (float*)d_out;

    float *qkv;
    uint32_t *hidtf, *qkvwtf, *projwtf, *qhib, *qlob, *khib, *klob, *vtf, *attntf;
    cudaGetSymbolAddress((void**)&hidtf,  g_hid_tf);
    cudaGetSymbolAddress((void**)&qkvwtf, g_qkvw_tf);
    cudaGetSymbolAddress((void**)&projwtf,g_projw_tf);
    cudaGetSymbolAddress((void**)&qkv,    g_qkv);
    cudaGetSymbolAddress((void**)&qhib,   g_qhib);
    cudaGetSymbolAddress((void**)&qlob,   g_qlob);
    cudaGetSymbolAddress((void**)&khib,   g_khib);
    cudaGetSymbolAddress((void**)&klob,   g_klob);
    cudaGetSymbolAddress((void**)&vtf,    g_vtf);
    cudaGetSymbolAddress((void**)&attntf, g_attn_tf);

    const size_t attn_smem = ATT_SMEM_WORDS * sizeof(uint32_t);
    static bool attr_done = false;
    if (!attr_done) {
        cudaFuncSetAttribute(tgemm128_kernel<3 * D, D>,
                             cudaFuncAttributeMaxDynamicSharedMemorySize, GEMM_SMEM1);
        cudaFuncSetAttribute(tgemm256_kernel<D, D>,
                             cudaFuncAttributeMaxDynamicSharedMemorySize, GEMM_SMEM2);
        cudaFuncSetAttribute(attn_mma_kernel,
                             cudaFuncAttributeMaxDynamicSharedMemorySize, (int)attn_smem);
        attr_done = true;
    }

    // 0) merged converts
    convert_all_kernel<<<(CVT_TOT + 255) / 256, 256>>>(
        hidden, qkv_w, proj_w, hidtf, qkvwtf, projwtf);

    // 1) QKV GEMM + bias
    tgemm128_kernel<3 * D, D><<<dim3((3 * D) / 128, N_TOK / 128), 256, GEMM_SMEM1>>>(
        hidtf, qkvwtf, qkv_b, qkv);

    // 2) RoPE + split
    rope_split_kernel<<<(N_TOK * H * WPR + 255) / 256, 256>>>(
        qkv, cosNK, sinNK, qhib, qlob, khib, klob, vtf);

    // 3) attention (KTK=64, interior fast path)
    attn_mma_kernel<<<dim3(N_TOK / QTQ, H), 128, attn_smem>>>(
        qhib, qlob, khib, klob, vtf, cu, attntf);

    // 4) projection GEMM + bias -> d_out
    tgemm256_kernel<D, D><<<dim3(D / 256, N_TOK / 128), 256, GEMM_SMEM2>>>(
        attntf, projwtf, proj_b, out);
}